// round 14
// baseline (speedup 1.0000x reference)
#include <cuda_runtime.h>
#include <cuda_bf16.h>
#include <cstdint>

// ---------------------------------------------------------------------------
// Problem constants
// ---------------------------------------------------------------------------
#define B_   8
#define LQ_  2048
#define LK_  2048
#define DQ_  1024
#define DK_  1024
#define DV_  1024

constexpr size_t NQ  = (size_t)B_ * LQ_ * DQ_;
constexpr size_t NKV = (size_t)B_ * LK_ * DK_;
constexpr size_t NS  = (size_t)B_ * LQ_ * LK_;
constexpr size_t NW  = (size_t)DK_ * DQ_;
constexpr size_t NM  = (size_t)B_ * LK_ * DK_;   // Mt = K @ W^T : [b][s][d]

// Scratch (__device__ globals: allocation-free rule; zero-initialized)
__device__ __align__(256) __nv_bfloat16 g_Qhi[NQ],  g_Qlo[NQ];    // split queries
__device__ __align__(256) __nv_bfloat16 g_Khi[NKV], g_Klo[NKV];   // split keys
__device__ __align__(256) __nv_bfloat16 g_Whi[NW],  g_Wlo[NW];    // split Wq (native [d][k])
__device__ __align__(256) __nv_bfloat16 g_Mthi[NM], g_Mtlo[NM];   // split Mt [b][s][d]
__device__ __align__(256) __nv_bfloat16 g_Vthi[NKV], g_Vtlo[NKV]; // split values^T [b][v][s]
__device__ __align__(256) float         g_S[NS];                  // scores
__device__ __align__(256) __nv_bfloat16 g_Phi[NS], g_Plo[NS];     // split probs (bf16)

// ---------------------------------------------------------------------------
// Helpers
// ---------------------------------------------------------------------------
__device__ __forceinline__ unsigned smem_u32(const void* p) {
    unsigned r;
    asm("{.reg .u64 t; cvta.to.shared.u64 t, %1; cvt.u32.u64 %0, t;}" : "=r"(r) : "l"(p));
    return r;
}
#define SWZ(b) ((b) ^ (((b) >> 3) & 0x30))

#define CPA(dst, src) \
    asm volatile("cp.async.cg.shared.global [%0], [%1], 16;\n" :: "r"(dst), "l"(src))
#define LDSM4(r0, r1, r2, r3, addr) \
    asm volatile("ldmatrix.sync.aligned.m8n8.x4.shared.b16 {%0,%1,%2,%3}, [%4];\n" \
                 : "=r"(r0), "=r"(r1), "=r"(r2), "=r"(r3) : "r"(addr))
#define MMA(d, a, bb) \
    asm volatile("mma.sync.aligned.m16n8k16.row.col.f32.bf16.bf16.f32 " \
                 "{%0,%1,%2,%3},{%4,%5,%6,%7},{%8,%9},{%0,%1,%2,%3};\n" \
                 : "+f"((d)[0]), "+f"((d)[1]), "+f"((d)[2]), "+f"((d)[3]) \
                 : "r"((a)[0]), "r"((a)[1]), "r"((a)[2]), "r"((a)[3]), \
                   "r"((bb)[0]), "r"((bb)[1]))

// ---------------------------------------------------------------------------
// 3-pass split-bf16 GEMM:  C = alpha * (Ahi+Alo) @ (Bhi+Blo)^T  (A:[M,K], B:[N,K])
// BM=BN=128, BK=32, 256 threads, 8 warps (2x4), warp tile 64x32.
// cp.async 3-stage pipeline (32KB stages), SW64 swizzle, ldmatrix loads.
// __launch_bounds__(256, 2) pins the 2-CTA/SM regime (the proven mechanism).
// GRID: x = batch (fastest-varying -> interleaves per-batch K-lengths/mask
//       skips within every wave, balancing the tail), y = M-tile, z = N-tile.
// Passes: Ah*Bh + Al*Bh + Ah*Bl.
// SKIPM: skip M-tiles >= lens[b].  SKIPN: skip N-tiles >= lens[b].
// KBOUND: clip K loop to round32(lens[b]).  SPLITOUT: write hi/lo bf16 arrays.
// ---------------------------------------------------------------------------
constexpr int BM = 128, BN = 128;
constexpr int STAGE  = 32768;     // bytes per pipeline stage (4 x 8KB tiles)
constexpr int NSTG   = 3;
constexpr int OFF_AH = 0, OFF_AL = 8192, OFF_BH = 16384, OFF_BL = 24576;
constexpr int GSMEM  = NSTG * STAGE;   // 96 KB -> 2 CTAs/SM (192 <= 227 KB)

template<bool SKIPM, bool SKIPN, bool KBOUND, bool SPLITOUT>
__global__ __launch_bounds__(256, 2)
void mma_gemm(const __nv_bfloat16* __restrict__ Ahi, const __nv_bfloat16* __restrict__ Alo,
              const __nv_bfloat16* __restrict__ Bh,  const __nv_bfloat16* __restrict__ Bl,
              float* __restrict__ C,
              __nv_bfloat16* __restrict__ Chi, __nv_bfloat16* __restrict__ Clo,
              int N, int K,
              long long sA, long long sB, long long sC,
              float alpha, const int* __restrict__ lens)
{
    const int b = blockIdx.x;                        // batch fastest-varying
    int L = 0;
    if (SKIPM || SKIPN || KBOUND) L = lens[b];
    if (SKIPM && (int)blockIdx.y * BM >= L) return;
    if (SKIPN && (int)blockIdx.z * BN >= L) return;
    int Keff = K;
    if (KBOUND) { int r = (L + 31) & ~31; Keff = r < K ? r : K; }
    const int ntiles = Keff >> 5;

    extern __shared__ char smem[];
    const unsigned sb = smem_u32(smem);

    const int tid = threadIdx.x, lane = tid & 31, wid = tid >> 5;
    const int wm = wid >> 2, wn = wid & 3;           // warp grid 2(m) x 4(n)
    const long long m0 = (long long)blockIdx.y * BM;
    const long long n0 = (long long)blockIdx.z * BN;

    Ahi += (long long)b * sA;  Alo += (long long)b * sA;
    Bh  += (long long)b * sB;  Bl  += (long long)b * sB;

    // ---- staging: thread owns 2 (row, 16B-chunk) slots per 128x32 tile ----
    const int srow = tid >> 2, sch = tid & 3;
    const unsigned d0 = SWZ((unsigned)(srow * 64 + sch * 16));
    const unsigned d1 = SWZ((unsigned)((srow + 64) * 64 + sch * 16));
    const __nv_bfloat16* pAh0 = Ahi + (m0 + srow)      * (long long)K + sch * 8;
    const __nv_bfloat16* pAh1 = Ahi + (m0 + srow + 64) * (long long)K + sch * 8;
    const __nv_bfloat16* pAl0 = Alo + (m0 + srow)      * (long long)K + sch * 8;
    const __nv_bfloat16* pAl1 = Alo + (m0 + srow + 64) * (long long)K + sch * 8;
    const __nv_bfloat16* pBh0 = Bh  + (n0 + srow)      * (long long)K + sch * 8;
    const __nv_bfloat16* pBh1 = Bh  + (n0 + srow + 64) * (long long)K + sch * 8;
    const __nv_bfloat16* pBl0 = Bl  + (n0 + srow)      * (long long)K + sch * 8;
    const __nv_bfloat16* pBl1 = Bl  + (n0 + srow + 64) * (long long)K + sch * 8;

#define ISSUE(stg, kt) do {                                                \
    unsigned s_ = sb + (unsigned)(stg) * STAGE; int ko_ = (kt) * 32;       \
    CPA(s_ + OFF_AH + d0, pAh0 + ko_); CPA(s_ + OFF_AH + d1, pAh1 + ko_); \
    CPA(s_ + OFF_AL + d0, pAl0 + ko_); CPA(s_ + OFF_AL + d1, pAl1 + ko_); \
    CPA(s_ + OFF_BH + d0, pBh0 + ko_); CPA(s_ + OFF_BH + d1, pBh1 + ko_); \
    CPA(s_ + OFF_BL + d0, pBl0 + ko_); CPA(s_ + OFF_BL + d1, pBl1 + ko_); \
    asm volatile("cp.async.commit_group;\n" ::); } while (0)

    float acc[4][4][4];
#pragma unroll
    for (int i = 0; i < 4; i++)
#pragma unroll
        for (int j = 0; j < 4; j++)
#pragma unroll
            for (int k = 0; k < 4; k++) acc[i][j][k] = 0.f;

    ISSUE(0, 0);
    if (ntiles > 1) ISSUE(1, 1);

    // fragment address components
    const int arow = lane & 15;
    const int ak2  = ((lane >> 4) & 1) * 16;
    const int g    = lane >> 3;
    const int brow = ((g >> 1) << 3) + (lane & 7);
    const int bk2  = (g & 1) * 16;

    for (int kt = 0; kt < ntiles; kt++) {
        if (kt + 2 < ntiles) ISSUE((kt + 2) % NSTG, kt + 2);
        const int rem = ntiles - 1 - kt;
        if (rem >= 2)      asm volatile("cp.async.wait_group 2;\n" ::);
        else if (rem == 1) asm volatile("cp.async.wait_group 1;\n" ::);
        else               asm volatile("cp.async.wait_group 0;\n" ::);
        __syncthreads();
        const unsigned base = sb + (unsigned)(kt % NSTG) * STAGE;

#pragma unroll
        for (int ks = 0; ks < 2; ks++) {
            unsigned ah[4][4], al[4][4], bh[4][2], bl[4][2];
#pragma unroll
            for (int mi = 0; mi < 4; mi++) {
                int row = wm * 64 + mi * 16 + arow;
                unsigned sw = SWZ((unsigned)(row * 64 + ks * 32 + ak2));
                LDSM4(ah[mi][0], ah[mi][1], ah[mi][2], ah[mi][3], base + OFF_AH + sw);
                LDSM4(al[mi][0], al[mi][1], al[mi][2], al[mi][3], base + OFF_AL + sw);
            }
#pragma unroll
            for (int bi = 0; bi < 2; bi++) {
                int row = wn * 32 + bi * 16 + brow;
                unsigned sw = SWZ((unsigned)(row * 64 + ks * 32 + bk2));
                LDSM4(bh[2*bi][0], bh[2*bi][1], bh[2*bi+1][0], bh[2*bi+1][1], base + OFF_BH + sw);
                LDSM4(bl[2*bi][0], bl[2*bi][1], bl[2*bi+1][0], bl[2*bi+1][1], base + OFF_BL + sw);
            }
#pragma unroll
            for (int mi = 0; mi < 4; mi++)
#pragma unroll
                for (int ni = 0; ni < 4; ni++) MMA(acc[mi][ni], ah[mi], bh[ni]);
#pragma unroll
            for (int mi = 0; mi < 4; mi++)
#pragma unroll
                for (int ni = 0; ni < 4; ni++) MMA(acc[mi][ni], al[mi], bh[ni]);
#pragma unroll
            for (int mi = 0; mi < 4; mi++)
#pragma unroll
                for (int ni = 0; ni < 4; ni++) MMA(acc[mi][ni], ah[mi], bl[ni]);
        }
        __syncthreads();
    }
#undef ISSUE

    // ---- epilogue ----
    const int erow = lane >> 2, ecol = (lane & 3) << 1;
#pragma unroll
    for (int mi = 0; mi < 4; mi++) {
        long long r0 = m0 + wm * 64 + mi * 16 + erow;
#pragma unroll
        for (int ni = 0; ni < 4; ni++) {
            long long c0 = n0 + wn * 32 + ni * 8 + ecol;
            float v0 = acc[mi][ni][0] * alpha, v1 = acc[mi][ni][1] * alpha;
            float v2 = acc[mi][ni][2] * alpha, v3 = acc[mi][ni][3] * alpha;
            size_t i0 = (size_t)((long long)b * sC + r0 * N + c0);
            size_t i1 = i0 + (size_t)8 * N;
            if (SPLITOUT) {
                __nv_bfloat162 h0, l0, h1, l1;
                h0.x = __float2bfloat16(v0); l0.x = __float2bfloat16(v0 - __bfloat162float(h0.x));
                h0.y = __float2bfloat16(v1); l0.y = __float2bfloat16(v1 - __bfloat162float(h0.y));
                h1.x = __float2bfloat16(v2); l1.x = __float2bfloat16(v2 - __bfloat162float(h1.x));
                h1.y = __float2bfloat16(v3); l1.y = __float2bfloat16(v3 - __bfloat162float(h1.y));
                *(__nv_bfloat162*)&Chi[i0] = h0;  *(__nv_bfloat162*)&Clo[i0] = l0;
                *(__nv_bfloat162*)&Chi[i1] = h1;  *(__nv_bfloat162*)&Clo[i1] = l1;
            } else {
                *(float2*)&C[i0] = make_float2(v0, v1);
                *(float2*)&C[i1] = make_float2(v2, v3);
            }
        }
    }
}

// ---------------------------------------------------------------------------
// Elementwise split: fp32 -> bf16 hi + bf16 lo
// ---------------------------------------------------------------------------
__global__ __launch_bounds__(256)
void split_kernel(const float4* __restrict__ src, __nv_bfloat162* __restrict__ hi,
                  __nv_bfloat162* __restrict__ lo, size_t n4)
{
    size_t i = (size_t)blockIdx.x * blockDim.x + threadIdx.x;
    const size_t stride = (size_t)gridDim.x * blockDim.x;
    for (; i < n4; i += stride) {
        float4 v = src[i];
        __nv_bfloat162 h0, h1, l0, l1;
        h0.x = __float2bfloat16(v.x); l0.x = __float2bfloat16(v.x - __bfloat162float(h0.x));
        h0.y = __float2bfloat16(v.y); l0.y = __float2bfloat16(v.y - __bfloat162float(h0.y));
        h1.x = __float2bfloat16(v.z); l1.x = __float2bfloat16(v.z - __bfloat162float(h1.x));
        h1.y = __float2bfloat16(v.w); l1.y = __float2bfloat16(v.w - __bfloat162float(h1.y));
        hi[2*i] = h0; hi[2*i+1] = h1;
        lo[2*i] = l0; lo[2*i+1] = l1;
    }
}

// ---------------------------------------------------------------------------
// Transpose + split: src[b][r][c] fp32 -> hi/lo[b][c][r] bf16.  64x64 tiles.
// ---------------------------------------------------------------------------
__global__ __launch_bounds__(256)
void transpose_split(const float* __restrict__ src, __nv_bfloat16* __restrict__ hi,
                     __nv_bfloat16* __restrict__ lo, int rows, int cols)
{
    __shared__ float t[64][65];
    const int b = blockIdx.z;
    const size_t off = (size_t)b * rows * cols;
    const int c0 = blockIdx.x * 64, r0 = blockIdx.y * 64;
    const int tid = threadIdx.x;

#pragma unroll
    for (int i = 0; i < 4; i++) {
        int fi = tid + 256 * i;
        int lr = fi >> 4, lc4 = fi & 15;
        float4 v = *(const float4*)&src[off + (size_t)(r0 + lr) * cols + c0 + lc4 * 4];
        t[lr][lc4 * 4 + 0] = v.x;  t[lr][lc4 * 4 + 1] = v.y;
        t[lr][lc4 * 4 + 2] = v.z;  t[lr][lc4 * 4 + 3] = v.w;
    }
    __syncthreads();

#pragma unroll
    for (int i = 0; i < 8; i++) {
        int ci = tid + 256 * i;
        int oc = ci >> 5, rs = ci & 31;
        float v0 = t[rs * 2][oc], v1 = t[rs * 2 + 1][oc];
        __nv_bfloat162 h, l;
        h.x = __float2bfloat16(v0); l.x = __float2bfloat16(v0 - __bfloat162float(h.x));
        h.y = __float2bfloat16(v1); l.y = __float2bfloat16(v1 - __bfloat162float(h.y));
        size_t o = off + (size_t)(c0 + oc) * rows + r0 + rs * 2;
        *(__nv_bfloat162*)&hi[o] = h;
        *(__nv_bfloat162*)&lo[o] = l;
    }
}

// ---------------------------------------------------------------------------
// Masked softmax: fp32 scores -> split-bf16 P. Loads only s<L, stores s<round32(L).
// Warp-shuffle reductions (2 __syncthreads total vs 16 for the smem tree).
// ---------------------------------------------------------------------------
__global__ __launch_bounds__(256)
void softmax_split(const float* __restrict__ S, __nv_bfloat16* __restrict__ Phi,
                   __nv_bfloat16* __restrict__ Plo, const int* __restrict__ lens)
{
    const int row = blockIdx.x;
    const int b   = row / LQ_;
    const int L   = lens[b];
    int Lr = (L + 31) & ~31;  Lr = Lr < LK_ ? Lr : LK_;
    const float* Sr = S + (size_t)row * LK_;
    __nv_bfloat16* Ph = Phi + (size_t)row * LK_;
    __nv_bfloat16* Pl = Plo + (size_t)row * LK_;

    const int tid = threadIdx.x, lane = tid & 31, wid = tid >> 5;
    __shared__ float red[8];

    float v[8];
    float m = -3.4e38f;
#pragma unroll
    for (int i = 0; i < 8; i++) {
        const int s = tid + i * 256;
        v[i] = (s < L) ? Sr[s] : 0.f;
        if (s < L) m = fmaxf(m, v[i]);
    }
#pragma unroll
    for (int o = 16; o > 0; o >>= 1)
        m = fmaxf(m, __shfl_xor_sync(0xFFFFFFFFu, m, o));
    if (lane == 0) red[wid] = m;
    __syncthreads();
    m = red[0];
#pragma unroll
    for (int w = 1; w < 8; w++) m = fmaxf(m, red[w]);
    __syncthreads();                      // protect red[] before reuse

    float sum = 0.f;
#pragma unroll
    for (int i = 0; i < 8; i++) {
        const int s = tid + i * 256;
        v[i] = (s < L) ? expf(v[i] - m) : 0.f;
        sum += v[i];
    }
#pragma unroll
    for (int o = 16; o > 0; o >>= 1)
        sum += __shfl_xor_sync(0xFFFFFFFFu, sum, o);
    if (lane == 0) red[wid] = sum;
    __syncthreads();
    float tot = red[0];
#pragma unroll
    for (int w = 1; w < 8; w++) tot += red[w];
    const float inv = 1.f / tot;

#pragma unroll
    for (int i = 0; i < 8; i++) {
        const int s = tid + i * 256;
        if (s < Lr) {
            float p = v[i] * inv;
            __nv_bfloat16 h = __float2bfloat16(p);
            Ph[s] = h;
            Pl[s] = __float2bfloat16(p - __bfloat162float(h));
        }
    }
}

// ---------------------------------------------------------------------------
// Launch:  Mt[b]=K[b]@W^T (skip masked rows) ; S=Q@Mt^T/32 (skip masked cols) ;
//          P=masked_softmax(S) ; out=P@V (K clipped at valid_len).  All bf16 3-pass.
// ---------------------------------------------------------------------------
extern "C" void kernel_launch(void* const* d_in, const int* in_sizes, int n_in,
                              void* d_out, int out_size)
{
    const float* queries = (const float*)d_in[0];
    const float* keys    = (const float*)d_in[1];
    const float* values  = (const float*)d_in[2];
    const int*   lens    = (const int*)  d_in[3];
    const float* Wq      = (const float*)d_in[4];
    float*       out     = (float*)d_out;

    void *pQhi, *pQlo, *pKhi, *pKlo, *pWhi, *pWlo, *pMthi, *pMtlo;
    void *pVthi, *pVtlo, *pS, *pPhi, *pPlo;
    cudaGetSymbolAddress(&pQhi,  g_Qhi);  cudaGetSymbolAddress(&pQlo,  g_Qlo);
    cudaGetSymbolAddress(&pKhi,  g_Khi);  cudaGetSymbolAddress(&pKlo,  g_Klo);
    cudaGetSymbolAddress(&pWhi,  g_Whi);  cudaGetSymbolAddress(&pWlo,  g_Wlo);
    cudaGetSymbolAddress(&pMthi, g_Mthi); cudaGetSymbolAddress(&pMtlo, g_Mtlo);
    cudaGetSymbolAddress(&pVthi, g_Vthi); cudaGetSymbolAddress(&pVtlo, g_Vtlo);
    cudaGetSymbolAddress(&pS,    g_S);
    cudaGetSymbolAddress(&pPhi,  g_Phi);  cudaGetSymbolAddress(&pPlo,  g_Plo);

    __nv_bfloat16 *Qhi = (__nv_bfloat16*)pQhi,  *Qlo = (__nv_bfloat16*)pQlo;
    __nv_bfloat16 *Khi = (__nv_bfloat16*)pKhi,  *Klo = (__nv_bfloat16*)pKlo;
    __nv_bfloat16 *Whi = (__nv_bfloat16*)pWhi,  *Wlo = (__nv_bfloat16*)pWlo;
    __nv_bfloat16 *Mthi = (__nv_bfloat16*)pMthi, *Mtlo = (__nv_bfloat16*)pMtlo;
    __nv_bfloat16 *Vthi = (__nv_bfloat16*)pVthi, *Vtlo = (__nv_bfloat16*)pVtlo;
    float *S = (float*)pS;
    __nv_bfloat16 *Phi = (__nv_bfloat16*)pPhi, *Plo = (__nv_bfloat16*)pPlo;

    cudaFuncSetAttribute(mma_gemm<true,  false, false, true >, cudaFuncAttributeMaxDynamicSharedMemorySize, GSMEM);
    cudaFuncSetAttribute(mma_gemm<false, true,  false, false>, cudaFuncAttributeMaxDynamicSharedMemorySize, GSMEM);
    cudaFuncSetAttribute(mma_gemm<false, false, true,  false>, cudaFuncAttributeMaxDynamicSharedMemorySize, GSMEM);

    // 0) prep: split Q, K, W (bf16); transpose+split V (bf16)
    split_kernel<<<2048, 256>>>((const float4*)queries, (__nv_bfloat162*)Qhi,
                                (__nv_bfloat162*)Qlo, NQ / 4);
    split_kernel<<<2048, 256>>>((const float4*)keys, (__nv_bfloat162*)Khi,
                                (__nv_bfloat162*)Klo, NKV / 4);
    split_kernel<<<512, 256>>>((const float4*)Wq, (__nv_bfloat162*)Whi,
                               (__nv_bfloat162*)Wlo, NW / 4);
    transpose_split<<<dim3(DV_/64, LK_/64, B_), 256>>>(values, Vthi, Vtlo, LK_, DV_);

    // 1) Mt[b] = K[b] @ W^T -> split bf16 [s][d]; skip M-tiles >= L
    //    grid: x=batch (interleaved), y=M-tile, z=N-tile
    mma_gemm<true, false, false, true><<<dim3(B_, LK_/BM, DK_/BN), 256, GSMEM>>>(
        Khi, Klo, Whi, Wlo, nullptr, Mthi, Mtlo,
        DK_, DK_,
        (long long)LK_ * DK_, 0LL, (long long)LK_ * DK_,
        1.0f, lens);

    // 2) S[b] = Q[b] @ Mt[b]^T / 32   (skip masked N-tiles)
    mma_gemm<false, true, false, false><<<dim3(B_, LQ_/BM, LK_/BN), 256, GSMEM>>>(
        Qhi, Qlo, Mthi, Mtlo, S, nullptr, nullptr,
        LK_, DQ_,
        (long long)LQ_ * DQ_, (long long)LK_ * DK_, (long long)LQ_ * LK_,
        0.03125f, lens);

    // 3) Masked softmax -> split bf16 P (bounded IO, shuffle reductions)
    softmax_split<<<B_ * LQ_, 256>>>(S, Phi, Plo, lens);

    // 4) out[b] = P[b] @ Vt[b]^T-form  (bf16 3-pass, K clipped at valid_len)
    mma_gemm<false, false, true, false><<<dim3(B_, LQ_/BM, DV_/BN), 256, GSMEM>>>(
        Phi, Plo, Vthi, Vtlo, out, nullptr, nullptr,
        DV_, LK_,
        (long long)LQ_ * LK_, (long long)DV_ * LK_, (long long)LQ_ * DV_,
        1.0f, lens);
}

// round 15
// speedup vs baseline: 1.0436x; 1.0436x over previous
#include <cuda_runtime.h>
#include <cuda_bf16.h>
#include <cstdint>

// ---------------------------------------------------------------------------
// Problem constants
// ---------------------------------------------------------------------------
#define B_   8
#define LQ_  2048
#define LK_  2048
#define DQ_  1024
#define DK_  1024
#define DV_  1024

constexpr size_t NQ  = (size_t)B_ * LQ_ * DQ_;
constexpr size_t NKV = (size_t)B_ * LK_ * DK_;
constexpr size_t NS  = (size_t)B_ * LQ_ * LK_;
constexpr size_t NW  = (size_t)DK_ * DQ_;
constexpr size_t NM  = (size_t)B_ * LK_ * DK_;   // Mt = K @ W^T : [b][s][d]

// Scratch (__device__ globals: allocation-free rule; zero-initialized)
__device__ __align__(256) __nv_bfloat16 g_Qhi[NQ],  g_Qlo[NQ];    // split queries
__device__ __align__(256) __nv_bfloat16 g_Khi[NKV], g_Klo[NKV];   // split keys
__device__ __align__(256) __nv_bfloat16 g_Whi[NW],  g_Wlo[NW];    // split Wq (native [d][k])
__device__ __align__(256) __nv_bfloat16 g_Mthi[NM], g_Mtlo[NM];   // split Mt [b][s][d]
__device__ __align__(256) __nv_bfloat16 g_Vthi[NKV], g_Vtlo[NKV]; // split values^T [b][v][s]
__device__ __align__(256) float         g_S[NS];                  // scores
__device__ __align__(256) __nv_bfloat16 g_Phi[NS], g_Plo[NS];     // split probs (bf16)

// ---------------------------------------------------------------------------
// Helpers
// ---------------------------------------------------------------------------
__device__ __forceinline__ unsigned smem_u32(const void* p) {
    unsigned r;
    asm("{.reg .u64 t; cvta.to.shared.u64 t, %1; cvt.u32.u64 %0, t;}" : "=r"(r) : "l"(p));
    return r;
}
#define SWZ(b) ((b) ^ (((b) >> 3) & 0x30))

#define CPA(dst, src) \
    asm volatile("cp.async.cg.shared.global [%0], [%1], 16;\n" :: "r"(dst), "l"(src))
#define LDSM4(r0, r1, r2, r3, addr) \
    asm volatile("ldmatrix.sync.aligned.m8n8.x4.shared.b16 {%0,%1,%2,%3}, [%4];\n" \
                 : "=r"(r0), "=r"(r1), "=r"(r2), "=r"(r3) : "r"(addr))
#define MMA(d, a, bb) \
    asm volatile("mma.sync.aligned.m16n8k16.row.col.f32.bf16.bf16.f32 " \
                 "{%0,%1,%2,%3},{%4,%5,%6,%7},{%8,%9},{%0,%1,%2,%3};\n" \
                 : "+f"((d)[0]), "+f"((d)[1]), "+f"((d)[2]), "+f"((d)[3]) \
                 : "r"((a)[0]), "r"((a)[1]), "r"((a)[2]), "r"((a)[3]), \
                   "r"((bb)[0]), "r"((bb)[1]))

// ---------------------------------------------------------------------------
// 3-pass split-bf16 GEMM:  C = alpha * (Ahi+Alo) @ (Bhi+Blo)^T  (A:[M,K], B:[N,K])
// BM=BN=128, BK=32, 256 threads, 8 warps (2x4), warp tile 64x32.
// cp.async 3-stage pipeline (32KB stages), SW64 swizzle, ldmatrix loads.
// __launch_bounds__(256, 2) pins the 2-CTA/SM regime (the proven mechanism).
// Grid: x = N-tile, y = M-tile, z = batch (the 801us winner's mapping).
// Passes: Ah*Bh + Al*Bh + Ah*Bl.
// SKIPM: skip M-tiles >= lens[b].  SKIPN: skip N-tiles >= lens[b].
// KBOUND: clip K loop to round32(lens[b]).  SPLITOUT: write hi/lo bf16 arrays.
// ---------------------------------------------------------------------------
constexpr int BM = 128, BN = 128;
constexpr int STAGE  = 32768;     // bytes per pipeline stage (4 x 8KB tiles)
constexpr int NSTG   = 3;
constexpr int OFF_AH = 0, OFF_AL = 8192, OFF_BH = 16384, OFF_BL = 24576;
constexpr int GSMEM  = NSTG * STAGE;   // 96 KB -> 2 CTAs/SM (192 <= 227 KB)

template<bool SKIPM, bool SKIPN, bool KBOUND, bool SPLITOUT>
__global__ __launch_bounds__(256, 2)
void mma_gemm(const __nv_bfloat16* __restrict__ Ahi, const __nv_bfloat16* __restrict__ Alo,
              const __nv_bfloat16* __restrict__ Bh,  const __nv_bfloat16* __restrict__ Bl,
              float* __restrict__ C,
              __nv_bfloat16* __restrict__ Chi, __nv_bfloat16* __restrict__ Clo,
              int N, int K,
              long long sA, long long sB, long long sC,
              float alpha, const int* __restrict__ lens)
{
    const int b = blockIdx.z;
    int L = 0;
    if (SKIPM || SKIPN || KBOUND) L = lens[b];
    if (SKIPM && (int)blockIdx.y * BM >= L) return;
    if (SKIPN && (int)blockIdx.x * BN >= L) return;
    int Keff = K;
    if (KBOUND) { int r = (L + 31) & ~31; Keff = r < K ? r : K; }
    const int ntiles = Keff >> 5;

    extern __shared__ char smem[];
    const unsigned sb = smem_u32(smem);

    const int tid = threadIdx.x, lane = tid & 31, wid = tid >> 5;
    const int wm = wid >> 2, wn = wid & 3;           // warp grid 2(m) x 4(n)
    const long long m0 = (long long)blockIdx.y * BM;
    const long long n0 = (long long)blockIdx.x * BN;

    Ahi += (long long)b * sA;  Alo += (long long)b * sA;
    Bh  += (long long)b * sB;  Bl  += (long long)b * sB;

    // ---- staging: thread owns 2 (row, 16B-chunk) slots per 128x32 tile ----
    const int srow = tid >> 2, sch = tid & 3;
    const unsigned d0 = SWZ((unsigned)(srow * 64 + sch * 16));
    const unsigned d1 = SWZ((unsigned)((srow + 64) * 64 + sch * 16));
    const __nv_bfloat16* pAh0 = Ahi + (m0 + srow)      * (long long)K + sch * 8;
    const __nv_bfloat16* pAh1 = Ahi + (m0 + srow + 64) * (long long)K + sch * 8;
    const __nv_bfloat16* pAl0 = Alo + (m0 + srow)      * (long long)K + sch * 8;
    const __nv_bfloat16* pAl1 = Alo + (m0 + srow + 64) * (long long)K + sch * 8;
    const __nv_bfloat16* pBh0 = Bh  + (n0 + srow)      * (long long)K + sch * 8;
    const __nv_bfloat16* pBh1 = Bh  + (n0 + srow + 64) * (long long)K + sch * 8;
    const __nv_bfloat16* pBl0 = Bl  + (n0 + srow)      * (long long)K + sch * 8;
    const __nv_bfloat16* pBl1 = Bl  + (n0 + srow + 64) * (long long)K + sch * 8;

#define ISSUE(stg, kt) do {                                                \
    unsigned s_ = sb + (unsigned)(stg) * STAGE; int ko_ = (kt) * 32;       \
    CPA(s_ + OFF_AH + d0, pAh0 + ko_); CPA(s_ + OFF_AH + d1, pAh1 + ko_); \
    CPA(s_ + OFF_AL + d0, pAl0 + ko_); CPA(s_ + OFF_AL + d1, pAl1 + ko_); \
    CPA(s_ + OFF_BH + d0, pBh0 + ko_); CPA(s_ + OFF_BH + d1, pBh1 + ko_); \
    CPA(s_ + OFF_BL + d0, pBl0 + ko_); CPA(s_ + OFF_BL + d1, pBl1 + ko_); \
    asm volatile("cp.async.commit_group;\n" ::); } while (0)

    float acc[4][4][4];
#pragma unroll
    for (int i = 0; i < 4; i++)
#pragma unroll
        for (int j = 0; j < 4; j++)
#pragma unroll
            for (int k = 0; k < 4; k++) acc[i][j][k] = 0.f;

    ISSUE(0, 0);
    if (ntiles > 1) ISSUE(1, 1);

    // fragment address components
    const int arow = lane & 15;
    const int ak2  = ((lane >> 4) & 1) * 16;
    const int g    = lane >> 3;
    const int brow = ((g >> 1) << 3) + (lane & 7);
    const int bk2  = (g & 1) * 16;

    for (int kt = 0; kt < ntiles; kt++) {
        if (kt + 2 < ntiles) ISSUE((kt + 2) % NSTG, kt + 2);
        const int rem = ntiles - 1 - kt;
        if (rem >= 2)      asm volatile("cp.async.wait_group 2;\n" ::);
        else if (rem == 1) asm volatile("cp.async.wait_group 1;\n" ::);
        else               asm volatile("cp.async.wait_group 0;\n" ::);
        __syncthreads();
        const unsigned base = sb + (unsigned)(kt % NSTG) * STAGE;

#pragma unroll
        for (int ks = 0; ks < 2; ks++) {
            unsigned ah[4][4], al[4][4], bh[4][2], bl[4][2];
#pragma unroll
            for (int mi = 0; mi < 4; mi++) {
                int row = wm * 64 + mi * 16 + arow;
                unsigned sw = SWZ((unsigned)(row * 64 + ks * 32 + ak2));
                LDSM4(ah[mi][0], ah[mi][1], ah[mi][2], ah[mi][3], base + OFF_AH + sw);
                LDSM4(al[mi][0], al[mi][1], al[mi][2], al[mi][3], base + OFF_AL + sw);
            }
#pragma unroll
            for (int bi = 0; bi < 2; bi++) {
                int row = wn * 32 + bi * 16 + brow;
                unsigned sw = SWZ((unsigned)(row * 64 + ks * 32 + bk2));
                LDSM4(bh[2*bi][0], bh[2*bi][1], bh[2*bi+1][0], bh[2*bi+1][1], base + OFF_BH + sw);
                LDSM4(bl[2*bi][0], bl[2*bi][1], bl[2*bi+1][0], bl[2*bi+1][1], base + OFF_BL + sw);
            }
#pragma unroll
            for (int mi = 0; mi < 4; mi++)
#pragma unroll
                for (int ni = 0; ni < 4; ni++) MMA(acc[mi][ni], ah[mi], bh[ni]);
#pragma unroll
            for (int mi = 0; mi < 4; mi++)
#pragma unroll
                for (int ni = 0; ni < 4; ni++) MMA(acc[mi][ni], al[mi], bh[ni]);
#pragma unroll
            for (int mi = 0; mi < 4; mi++)
#pragma unroll
                for (int ni = 0; ni < 4; ni++) MMA(acc[mi][ni], ah[mi], bl[ni]);
        }
        __syncthreads();
    }
#undef ISSUE

    // ---- epilogue ----
    const int erow = lane >> 2, ecol = (lane & 3) << 1;
#pragma unroll
    for (int mi = 0; mi < 4; mi++) {
        long long r0 = m0 + wm * 64 + mi * 16 + erow;
#pragma unroll
        for (int ni = 0; ni < 4; ni++) {
            long long c0 = n0 + wn * 32 + ni * 8 + ecol;
            float v0 = acc[mi][ni][0] * alpha, v1 = acc[mi][ni][1] * alpha;
            float v2 = acc[mi][ni][2] * alpha, v3 = acc[mi][ni][3] * alpha;
            size_t i0 = (size_t)((long long)b * sC + r0 * N + c0);
            size_t i1 = i0 + (size_t)8 * N;
            if (SPLITOUT) {
                __nv_bfloat162 h0, l0, h1, l1;
                h0.x = __float2bfloat16(v0); l0.x = __float2bfloat16(v0 - __bfloat162float(h0.x));
                h0.y = __float2bfloat16(v1); l0.y = __float2bfloat16(v1 - __bfloat162float(h0.y));
                h1.x = __float2bfloat16(v2); l1.x = __float2bfloat16(v2 - __bfloat162float(h1.x));
                h1.y = __float2bfloat16(v3); l1.y = __float2bfloat16(v3 - __bfloat162float(h1.y));
                *(__nv_bfloat162*)&Chi[i0] = h0;  *(__nv_bfloat162*)&Clo[i0] = l0;
                *(__nv_bfloat162*)&Chi[i1] = h1;  *(__nv_bfloat162*)&Clo[i1] = l1;
            } else {
                *(float2*)&C[i0] = make_float2(v0, v1);
                *(float2*)&C[i1] = make_float2(v2, v3);
            }
        }
    }
}

// ---------------------------------------------------------------------------
// Elementwise split: fp32 -> bf16 hi + bf16 lo (unbounded; Q and W)
// ---------------------------------------------------------------------------
__global__ __launch_bounds__(256)
void split_kernel(const float4* __restrict__ src, __nv_bfloat162* __restrict__ hi,
                  __nv_bfloat162* __restrict__ lo, size_t n4)
{
    size_t i = (size_t)blockIdx.x * blockDim.x + threadIdx.x;
    const size_t stride = (size_t)gridDim.x * blockDim.x;
    for (; i < n4; i += stride) {
        float4 v = src[i];
        __nv_bfloat162 h0, h1, l0, l1;
        h0.x = __float2bfloat16(v.x); l0.x = __float2bfloat16(v.x - __bfloat162float(h0.x));
        h0.y = __float2bfloat16(v.y); l0.y = __float2bfloat16(v.y - __bfloat162float(h0.y));
        h1.x = __float2bfloat16(v.z); l1.x = __float2bfloat16(v.z - __bfloat162float(h1.x));
        h1.y = __float2bfloat16(v.w); l1.y = __float2bfloat16(v.w - __bfloat162float(h1.y));
        hi[2*i] = h0; hi[2*i+1] = h1;
        lo[2*i] = l0; lo[2*i+1] = l1;
    }
}

// ---------------------------------------------------------------------------
// Mask-bounded row split for K [b][s][d]: rows s >= round128(lens[b]) are never
// read by the Mt GEMM (SKIPM) -> skip those blocks.  4 rows per block.
// ---------------------------------------------------------------------------
__global__ __launch_bounds__(256)
void split_rows_kernel(const float4* __restrict__ src, __nv_bfloat162* __restrict__ hi,
                       __nv_bfloat162* __restrict__ lo, const int* __restrict__ lens)
{
    const int b = blockIdx.y;
    const int row0 = blockIdx.x * 4;
    const int L = lens[b];
    if (row0 >= ((L + 127) & ~127)) return;

    constexpr int C4 = DK_ / 4;           // 256 float4 per row
    const size_t base = ((size_t)b * LK_ + row0) * C4;   // in float4 units
    const int tid = threadIdx.x;
#pragma unroll
    for (int j = 0; j < 4; j++) {
        size_t i = base + (size_t)j * 256 + tid;
        float4 v = src[i];
        __nv_bfloat162 h0, h1, l0, l1;
        h0.x = __float2bfloat16(v.x); l0.x = __float2bfloat16(v.x - __bfloat162float(h0.x));
        h0.y = __float2bfloat16(v.y); l0.y = __float2bfloat16(v.y - __bfloat162float(h0.y));
        h1.x = __float2bfloat16(v.z); l1.x = __float2bfloat16(v.z - __bfloat162float(h1.x));
        h1.y = __float2bfloat16(v.w); l1.y = __float2bfloat16(v.w - __bfloat162float(h1.y));
        hi[2*i] = h0; hi[2*i+1] = h1;
        lo[2*i] = l0; lo[2*i+1] = l1;
    }
}

// ---------------------------------------------------------------------------
// Transpose + split: src[b][r][c] fp32 -> hi/lo[b][c][r] bf16.  64x64 tiles.
// Mask-bounded: tiles with r0 >= round32(lens[b]) produce s-positions the PV
// GEMM's K-clip never reads -> skip.
// ---------------------------------------------------------------------------
__global__ __launch_bounds__(256)
void transpose_split(const float* __restrict__ src, __nv_bfloat16* __restrict__ hi,
                     __nv_bfloat16* __restrict__ lo, int rows, int cols,
                     const int* __restrict__ lens)
{
    const int b = blockIdx.z;
    const int r0 = blockIdx.y * 64;
    if (lens) {
        const int L = lens[b];
        if (r0 >= ((L + 31) & ~31)) return;
    }
    __shared__ float t[64][65];
    const size_t off = (size_t)b * rows * cols;
    const int c0 = blockIdx.x * 64;
    const int tid = threadIdx.x;

#pragma unroll
    for (int i = 0; i < 4; i++) {
        int fi = tid + 256 * i;
        int lr = fi >> 4, lc4 = fi & 15;
        float4 v = *(const float4*)&src[off + (size_t)(r0 + lr) * cols + c0 + lc4 * 4];
        t[lr][lc4 * 4 + 0] = v.x;  t[lr][lc4 * 4 + 1] = v.y;
        t[lr][lc4 * 4 + 2] = v.z;  t[lr][lc4 * 4 + 3] = v.w;
    }
    __syncthreads();

#pragma unroll
    for (int i = 0; i < 8; i++) {
        int ci = tid + 256 * i;
        int oc = ci >> 5, rs = ci & 31;
        float v0 = t[rs * 2][oc], v1 = t[rs * 2 + 1][oc];
        __nv_bfloat162 h, l;
        h.x = __float2bfloat16(v0); l.x = __float2bfloat16(v0 - __bfloat162float(h.x));
        h.y = __float2bfloat16(v1); l.y = __float2bfloat16(v1 - __bfloat162float(h.y));
        size_t o = off + (size_t)(c0 + oc) * rows + r0 + rs * 2;
        *(__nv_bfloat162*)&hi[o] = h;
        *(__nv_bfloat162*)&lo[o] = l;
    }
}

// ---------------------------------------------------------------------------
// Masked softmax: fp32 scores -> split-bf16 P. Loads only s<L, stores s<round32(L).
// Warp-shuffle reductions (2 __syncthreads total).
// ---------------------------------------------------------------------------
__global__ __launch_bounds__(256)
void softmax_split(const float* __restrict__ S, __nv_bfloat16* __restrict__ Phi,
                   __nv_bfloat16* __restrict__ Plo, const int* __restrict__ lens)
{
    const int row = blockIdx.x;
    const int b   = row / LQ_;
    const int L   = lens[b];
    int Lr = (L + 31) & ~31;  Lr = Lr < LK_ ? Lr : LK_;
    const float* Sr = S + (size_t)row * LK_;
    __nv_bfloat16* Ph = Phi + (size_t)row * LK_;
    __nv_bfloat16* Pl = Plo + (size_t)row * LK_;

    const int tid = threadIdx.x, lane = tid & 31, wid = tid >> 5;
    __shared__ float red[8];

    float v[8];
    float m = -3.4e38f;
#pragma unroll
    for (int i = 0; i < 8; i++) {
        const int s = tid + i * 256;
        v[i] = (s < L) ? Sr[s] : 0.f;
        if (s < L) m = fmaxf(m, v[i]);
    }
#pragma unroll
    for (int o = 16; o > 0; o >>= 1)
        m = fmaxf(m, __shfl_xor_sync(0xFFFFFFFFu, m, o));
    if (lane == 0) red[wid] = m;
    __syncthreads();
    m = red[0];
#pragma unroll
    for (int w = 1; w < 8; w++) m = fmaxf(m, red[w]);
    __syncthreads();                      // protect red[] before reuse

    float sum = 0.f;
#pragma unroll
    for (int i = 0; i < 8; i++) {
        const int s = tid + i * 256;
        v[i] = (s < L) ? expf(v[i] - m) : 0.f;
        sum += v[i];
    }
#pragma unroll
    for (int o = 16; o > 0; o >>= 1)
        sum += __shfl_xor_sync(0xFFFFFFFFu, sum, o);
    if (lane == 0) red[wid] = sum;
    __syncthreads();
    float tot = red[0];
#pragma unroll
    for (int w = 1; w < 8; w++) tot += red[w];
    const float inv = 1.f / tot;

#pragma unroll
    for (int i = 0; i < 8; i++) {
        const int s = tid + i * 256;
        if (s < Lr) {
            float p = v[i] * inv;
            __nv_bfloat16 h = __float2bfloat16(p);
            Ph[s] = h;
            Pl[s] = __float2bfloat16(p - __bfloat162float(h));
        }
    }
}

// ---------------------------------------------------------------------------
// Launch:  Mt[b]=K[b]@W^T (skip masked rows) ; S=Q@Mt^T/32 (skip masked cols) ;
//          P=masked_softmax(S) ; out=P@V (K clipped at valid_len).  All bf16 3-pass.
// ---------------------------------------------------------------------------
extern "C" void kernel_launch(void* const* d_in, const int* in_sizes, int n_in,
                              void* d_out, int out_size)
{
    const float* queries = (const float*)d_in[0];
    const float* keys    = (const float*)d_in[1];
    const float* values  = (const float*)d_in[2];
    const int*   lens    = (const int*)  d_in[3];
    const float* Wq      = (const float*)d_in[4];
    float*       out     = (float*)d_out;

    void *pQhi, *pQlo, *pKhi, *pKlo, *pWhi, *pWlo, *pMthi, *pMtlo;
    void *pVthi, *pVtlo, *pS, *pPhi, *pPlo;
    cudaGetSymbolAddress(&pQhi,  g_Qhi);  cudaGetSymbolAddress(&pQlo,  g_Qlo);
    cudaGetSymbolAddress(&pKhi,  g_Khi);  cudaGetSymbolAddress(&pKlo,  g_Klo);
    cudaGetSymbolAddress(&pWhi,  g_Whi);  cudaGetSymbolAddress(&pWlo,  g_Wlo);
    cudaGetSymbolAddress(&pMthi, g_Mthi); cudaGetSymbolAddress(&pMtlo, g_Mtlo);
    cudaGetSymbolAddress(&pVthi, g_Vthi); cudaGetSymbolAddress(&pVtlo, g_Vtlo);
    cudaGetSymbolAddress(&pS,    g_S);
    cudaGetSymbolAddress(&pPhi,  g_Phi);  cudaGetSymbolAddress(&pPlo,  g_Plo);

    __nv_bfloat16 *Qhi = (__nv_bfloat16*)pQhi,  *Qlo = (__nv_bfloat16*)pQlo;
    __nv_bfloat16 *Khi = (__nv_bfloat16*)pKhi,  *Klo = (__nv_bfloat16*)pKlo;
    __nv_bfloat16 *Whi = (__nv_bfloat16*)pWhi,  *Wlo = (__nv_bfloat16*)pWlo;
    __nv_bfloat16 *Mthi = (__nv_bfloat16*)pMthi, *Mtlo = (__nv_bfloat16*)pMtlo;
    __nv_bfloat16 *Vthi = (__nv_bfloat16*)pVthi, *Vtlo = (__nv_bfloat16*)pVtlo;
    float *S = (float*)pS;
    __nv_bfloat16 *Phi = (__nv_bfloat16*)pPhi, *Plo = (__nv_bfloat16*)pPlo;

    cudaFuncSetAttribute(mma_gemm<true,  false, false, true >, cudaFuncAttributeMaxDynamicSharedMemorySize, GSMEM);
    cudaFuncSetAttribute(mma_gemm<false, true,  false, false>, cudaFuncAttributeMaxDynamicSharedMemorySize, GSMEM);
    cudaFuncSetAttribute(mma_gemm<false, false, true,  false>, cudaFuncAttributeMaxDynamicSharedMemorySize, GSMEM);

    // 0) prep: split Q, W (full); K rows bounded by mask; V transpose bounded
    split_kernel<<<2048, 256>>>((const float4*)queries, (__nv_bfloat162*)Qhi,
                                (__nv_bfloat162*)Qlo, NQ / 4);
    split_rows_kernel<<<dim3(LK_/4, B_), 256>>>((const float4*)keys,
                                (__nv_bfloat162*)Khi, (__nv_bfloat162*)Klo, lens);
    split_kernel<<<512, 256>>>((const float4*)Wq, (__nv_bfloat162*)Whi,
                               (__nv_bfloat162*)Wlo, NW / 4);
    transpose_split<<<dim3(DV_/64, LK_/64, B_), 256>>>(values, Vthi, Vtlo, LK_, DV_, lens);

    // 1) Mt[b] = K[b] @ W^T -> split bf16 [s][d]; skip M-tiles >= L
    mma_gemm<true, false, false, true><<<dim3(DK_/BN, LK_/BM, B_), 256, GSMEM>>>(
        Khi, Klo, Whi, Wlo, nullptr, Mthi, Mtlo,
        DK_, DK_,
        (long long)LK_ * DK_, 0LL, (long long)LK_ * DK_,
        1.0f, lens);

    // 2) S[b] = Q[b] @ Mt[b]^T / 32   (skip masked N-tiles)
    mma_gemm<false, true, false, false><<<dim3(LK_/BN, LQ_/BM, B_), 256, GSMEM>>>(
        Qhi, Qlo, Mthi, Mtlo, S, nullptr, nullptr,
        LK_, DQ_,
        (long long)LQ_ * DQ_, (long long)LK_ * DK_, (long long)LQ_ * LK_,
        0.03125f, lens);

    // 3) Masked softmax -> split bf16 P (bounded IO, shuffle reductions)
    softmax_split<<<B_ * LQ_, 256>>>(S, Phi, Plo, lens);

    // 4) out[b] = P[b] @ Vt[b]^T-form  (bf16 3-pass, K clipped at valid_len)
    mma_gemm<false, false, true, false><<<dim3(DV_/BN, LQ_/BM, B_), 256, GSMEM>>>(
        Phi, Plo, Vthi, Vtlo, out, nullptr, nullptr,
        DV_, LK_,
        (long long)LQ_ * LK_, (long long)DV_ * LK_, (long long)LQ_ * DV_,
        1.0f, lens);
}

// round 16
// speedup vs baseline: 1.0493x; 1.0054x over previous
#include <cuda_runtime.h>
#include <cuda_bf16.h>
#include <cstdint>

// ---------------------------------------------------------------------------
// Problem constants
// ---------------------------------------------------------------------------
#define B_   8
#define LQ_  2048
#define LK_  2048
#define DQ_  1024
#define DK_  1024
#define DV_  1024

constexpr size_t NQ  = (size_t)B_ * LQ_ * DQ_;
constexpr size_t NKV = (size_t)B_ * LK_ * DK_;
constexpr size_t NS  = (size_t)B_ * LQ_ * LK_;
constexpr size_t NW  = (size_t)DK_ * DQ_;
constexpr size_t NM  = (size_t)B_ * LK_ * DK_;   // Mt = K @ W^T : [b][s][d]

// Scratch (__device__ globals: allocation-free rule; zero-initialized)
__device__ __align__(256) __nv_bfloat16 g_Qhi[NQ],  g_Qlo[NQ];    // split queries
__device__ __align__(256) __nv_bfloat16 g_Khi[NKV], g_Klo[NKV];   // split keys
__device__ __align__(256) __nv_bfloat16 g_Whi[NW],  g_Wlo[NW];    // split Wq (native [d][k])
__device__ __align__(256) __nv_bfloat16 g_Mthi[NM], g_Mtlo[NM];   // split Mt [b][s][d]
__device__ __align__(256) __nv_bfloat16 g_Vthi[NKV], g_Vtlo[NKV]; // split values^T [b][v][s]
__device__ __align__(256) float         g_S[NS];                  // scores
__device__ __align__(256) __nv_bfloat16 g_Phi[NS], g_Plo[NS];     // split probs (bf16)

// ---------------------------------------------------------------------------
// Helpers
// ---------------------------------------------------------------------------
__device__ __forceinline__ unsigned smem_u32(const void* p) {
    unsigned r;
    asm("{.reg .u64 t; cvta.to.shared.u64 t, %1; cvt.u32.u64 %0, t;}" : "=r"(r) : "l"(p));
    return r;
}
#define SWZ(b) ((b) ^ (((b) >> 3) & 0x30))

#define CPA(dst, src) \
    asm volatile("cp.async.cg.shared.global [%0], [%1], 16;\n" :: "r"(dst), "l"(src))
#define LDSM4(r0, r1, r2, r3, addr) \
    asm volatile("ldmatrix.sync.aligned.m8n8.x4.shared.b16 {%0,%1,%2,%3}, [%4];\n" \
                 : "=r"(r0), "=r"(r1), "=r"(r2), "=r"(r3) : "r"(addr))
#define MMA(d, a, bb) \
    asm volatile("mma.sync.aligned.m16n8k16.row.col.f32.bf16.bf16.f32 " \
                 "{%0,%1,%2,%3},{%4,%5,%6,%7},{%8,%9},{%0,%1,%2,%3};\n" \
                 : "+f"((d)[0]), "+f"((d)[1]), "+f"((d)[2]), "+f"((d)[3]) \
                 : "r"((a)[0]), "r"((a)[1]), "r"((a)[2]), "r"((a)[3]), \
                   "r"((bb)[0]), "r"((bb)[1]))

// ---------------------------------------------------------------------------
// 3-pass split-bf16 GEMM:  C = alpha * (Ahi+Alo) @ (Bhi+Blo)^T  (A:[M,K], B:[N,K])
// BM=BN=128, BK=32, 256 threads, 8 warps (2x4), warp tile 64x32.
// cp.async 3-stage pipeline (32KB stages), SW64 swizzle, ldmatrix loads.
// __launch_bounds__(256, 2) pins the 2-CTA/SM regime (the proven mechanism).
// ONE __syncthreads per K-tile: wait -> sync -> issue(kt+2) -> compute(kt).
//   Safe because issue targets stage (kt-1)%3, which the top barrier proves
//   all warps finished reading (it was computed in iteration kt-1).
// Grid: x = N-tile, y = M-tile, z = batch (the proven mapping).
// Passes: Ah*Bh + Al*Bh + Ah*Bl.
// SKIPM: skip M-tiles >= lens[b].  SKIPN: skip N-tiles >= lens[b].
// KBOUND: clip K loop to round32(lens[b]).  SPLITOUT: write hi/lo bf16 arrays.
// ---------------------------------------------------------------------------
constexpr int BM = 128, BN = 128;
constexpr int STAGE  = 32768;     // bytes per pipeline stage (4 x 8KB tiles)
constexpr int NSTG   = 3;
constexpr int OFF_AH = 0, OFF_AL = 8192, OFF_BH = 16384, OFF_BL = 24576;
constexpr int GSMEM  = NSTG * STAGE;   // 96 KB -> 2 CTAs/SM (192 <= 227 KB)

template<bool SKIPM, bool SKIPN, bool KBOUND, bool SPLITOUT>
__global__ __launch_bounds__(256, 2)
void mma_gemm(const __nv_bfloat16* __restrict__ Ahi, const __nv_bfloat16* __restrict__ Alo,
              const __nv_bfloat16* __restrict__ Bh,  const __nv_bfloat16* __restrict__ Bl,
              float* __restrict__ C,
              __nv_bfloat16* __restrict__ Chi, __nv_bfloat16* __restrict__ Clo,
              int N, int K,
              long long sA, long long sB, long long sC,
              float alpha, const int* __restrict__ lens)
{
    const int b = blockIdx.z;
    int L = 0;
    if (SKIPM || SKIPN || KBOUND) L = lens[b];
    if (SKIPM && (int)blockIdx.y * BM >= L) return;
    if (SKIPN && (int)blockIdx.x * BN >= L) return;
    int Keff = K;
    if (KBOUND) { int r = (L + 31) & ~31; Keff = r < K ? r : K; }
    const int ntiles = Keff >> 5;

    extern __shared__ char smem[];
    const unsigned sb = smem_u32(smem);

    const int tid = threadIdx.x, lane = tid & 31, wid = tid >> 5;
    const int wm = wid >> 2, wn = wid & 3;           // warp grid 2(m) x 4(n)
    const long long m0 = (long long)blockIdx.y * BM;
    const long long n0 = (long long)blockIdx.x * BN;

    Ahi += (long long)b * sA;  Alo += (long long)b * sA;
    Bh  += (long long)b * sB;  Bl  += (long long)b * sB;

    // ---- staging: thread owns 2 (row, 16B-chunk) slots per 128x32 tile ----
    const int srow = tid >> 2, sch = tid & 3;
    const unsigned d0 = SWZ((unsigned)(srow * 64 + sch * 16));
    const unsigned d1 = SWZ((unsigned)((srow + 64) * 64 + sch * 16));
    const __nv_bfloat16* pAh0 = Ahi + (m0 + srow)      * (long long)K + sch * 8;
    const __nv_bfloat16* pAh1 = Ahi + (m0 + srow + 64) * (long long)K + sch * 8;
    const __nv_bfloat16* pAl0 = Alo + (m0 + srow)      * (long long)K + sch * 8;
    const __nv_bfloat16* pAl1 = Alo + (m0 + srow + 64) * (long long)K + sch * 8;
    const __nv_bfloat16* pBh0 = Bh  + (n0 + srow)      * (long long)K + sch * 8;
    const __nv_bfloat16* pBh1 = Bh  + (n0 + srow + 64) * (long long)K + sch * 8;
    const __nv_bfloat16* pBl0 = Bl  + (n0 + srow)      * (long long)K + sch * 8;
    const __nv_bfloat16* pBl1 = Bl  + (n0 + srow + 64) * (long long)K + sch * 8;

#define ISSUE(stg, kt) do {                                                \
    unsigned s_ = sb + (unsigned)(stg) * STAGE; int ko_ = (kt) * 32;       \
    CPA(s_ + OFF_AH + d0, pAh0 + ko_); CPA(s_ + OFF_AH + d1, pAh1 + ko_); \
    CPA(s_ + OFF_AL + d0, pAl0 + ko_); CPA(s_ + OFF_AL + d1, pAl1 + ko_); \
    CPA(s_ + OFF_BH + d0, pBh0 + ko_); CPA(s_ + OFF_BH + d1, pBh1 + ko_); \
    CPA(s_ + OFF_BL + d0, pBl0 + ko_); CPA(s_ + OFF_BL + d1, pBl1 + ko_); \
    asm volatile("cp.async.commit_group;\n" ::); } while (0)

    float acc[4][4][4];
#pragma unroll
    for (int i = 0; i < 4; i++)
#pragma unroll
        for (int j = 0; j < 4; j++)
#pragma unroll
            for (int k = 0; k < 4; k++) acc[i][j][k] = 0.f;

    ISSUE(0, 0);
    if (ntiles > 1) ISSUE(1, 1);

    // fragment address components
    const int arow = lane & 15;
    const int ak2  = ((lane >> 4) & 1) * 16;
    const int g    = lane >> 3;
    const int brow = ((g >> 1) << 3) + (lane & 7);
    const int bk2  = (g & 1) * 16;

    for (int kt = 0; kt < ntiles; kt++) {
        if (kt + 1 < ntiles) asm volatile("cp.async.wait_group 1;\n" ::);
        else                 asm volatile("cp.async.wait_group 0;\n" ::);
        __syncthreads();
        if (kt + 2 < ntiles) ISSUE((kt + 2) % NSTG, kt + 2);
        const unsigned base = sb + (unsigned)(kt % NSTG) * STAGE;

#pragma unroll
        for (int ks = 0; ks < 2; ks++) {
            unsigned ah[4][4], al[4][4], bh[4][2], bl[4][2];
#pragma unroll
            for (int mi = 0; mi < 4; mi++) {
                int row = wm * 64 + mi * 16 + arow;
                unsigned sw = SWZ((unsigned)(row * 64 + ks * 32 + ak2));
                LDSM4(ah[mi][0], ah[mi][1], ah[mi][2], ah[mi][3], base + OFF_AH + sw);
                LDSM4(al[mi][0], al[mi][1], al[mi][2], al[mi][3], base + OFF_AL + sw);
            }
#pragma unroll
            for (int bi = 0; bi < 2; bi++) {
                int row = wn * 32 + bi * 16 + brow;
                unsigned sw = SWZ((unsigned)(row * 64 + ks * 32 + bk2));
                LDSM4(bh[2*bi][0], bh[2*bi][1], bh[2*bi+1][0], bh[2*bi+1][1], base + OFF_BH + sw);
                LDSM4(bl[2*bi][0], bl[2*bi][1], bl[2*bi+1][0], bl[2*bi+1][1], base + OFF_BL + sw);
            }
#pragma unroll
            for (int mi = 0; mi < 4; mi++)
#pragma unroll
                for (int ni = 0; ni < 4; ni++) MMA(acc[mi][ni], ah[mi], bh[ni]);
#pragma unroll
            for (int mi = 0; mi < 4; mi++)
#pragma unroll
                for (int ni = 0; ni < 4; ni++) MMA(acc[mi][ni], al[mi], bh[ni]);
#pragma unroll
            for (int mi = 0; mi < 4; mi++)
#pragma unroll
                for (int ni = 0; ni < 4; ni++) MMA(acc[mi][ni], ah[mi], bl[ni]);
        }
    }
#undef ISSUE

    // ---- epilogue ----
    const int erow = lane >> 2, ecol = (lane & 3) << 1;
#pragma unroll
    for (int mi = 0; mi < 4; mi++) {
        long long r0 = m0 + wm * 64 + mi * 16 + erow;
#pragma unroll
        for (int ni = 0; ni < 4; ni++) {
            long long c0 = n0 + wn * 32 + ni * 8 + ecol;
            float v0 = acc[mi][ni][0] * alpha, v1 = acc[mi][ni][1] * alpha;
            float v2 = acc[mi][ni][2] * alpha, v3 = acc[mi][ni][3] * alpha;
            size_t i0 = (size_t)((long long)b * sC + r0 * N + c0);
            size_t i1 = i0 + (size_t)8 * N;
            if (SPLITOUT) {
                __nv_bfloat162 h0, l0, h1, l1;
                h0.x = __float2bfloat16(v0); l0.x = __float2bfloat16(v0 - __bfloat162float(h0.x));
                h0.y = __float2bfloat16(v1); l0.y = __float2bfloat16(v1 - __bfloat162float(h0.y));
                h1.x = __float2bfloat16(v2); l1.x = __float2bfloat16(v2 - __bfloat162float(h1.x));
                h1.y = __float2bfloat16(v3); l1.y = __float2bfloat16(v3 - __bfloat162float(h1.y));
                *(__nv_bfloat162*)&Chi[i0] = h0;  *(__nv_bfloat162*)&Clo[i0] = l0;
                *(__nv_bfloat162*)&Chi[i1] = h1;  *(__nv_bfloat162*)&Clo[i1] = l1;
            } else {
                *(float2*)&C[i0] = make_float2(v0, v1);
                *(float2*)&C[i1] = make_float2(v2, v3);
            }
        }
    }
}

// ---------------------------------------------------------------------------
// Elementwise split: fp32 -> bf16 hi + bf16 lo (unbounded; Q and W)
// ---------------------------------------------------------------------------
__global__ __launch_bounds__(256)
void split_kernel(const float4* __restrict__ src, __nv_bfloat162* __restrict__ hi,
                  __nv_bfloat162* __restrict__ lo, size_t n4)
{
    size_t i = (size_t)blockIdx.x * blockDim.x + threadIdx.x;
    const size_t stride = (size_t)gridDim.x * blockDim.x;
    for (; i < n4; i += stride) {
        float4 v = src[i];
        __nv_bfloat162 h0, h1, l0, l1;
        h0.x = __float2bfloat16(v.x); l0.x = __float2bfloat16(v.x - __bfloat162float(h0.x));
        h0.y = __float2bfloat16(v.y); l0.y = __float2bfloat16(v.y - __bfloat162float(h0.y));
        h1.x = __float2bfloat16(v.z); l1.x = __float2bfloat16(v.z - __bfloat162float(h1.x));
        h1.y = __float2bfloat16(v.w); l1.y = __float2bfloat16(v.w - __bfloat162float(h1.y));
        hi[2*i] = h0; hi[2*i+1] = h1;
        lo[2*i] = l0; lo[2*i+1] = l1;
    }
}

// ---------------------------------------------------------------------------
// Mask-bounded row split for K [b][s][d]: rows s >= round128(lens[b]) are never
// read by the Mt GEMM (SKIPM) -> skip those blocks.  4 rows per block.
// ---------------------------------------------------------------------------
__global__ __launch_bounds__(256)
void split_rows_kernel(const float4* __restrict__ src, __nv_bfloat162* __restrict__ hi,
                       __nv_bfloat162* __restrict__ lo, const int* __restrict__ lens)
{
    const int b = blockIdx.y;
    const int row0 = blockIdx.x * 4;
    const int L = lens[b];
    if (row0 >= ((L + 127) & ~127)) return;

    constexpr int C4 = DK_ / 4;           // 256 float4 per row
    const size_t base = ((size_t)b * LK_ + row0) * C4;   // in float4 units
    const int tid = threadIdx.x;
#pragma unroll
    for (int j = 0; j < 4; j++) {
        size_t i = base + (size_t)j * 256 + tid;
        float4 v = src[i];
        __nv_bfloat162 h0, h1, l0, l1;
        h0.x = __float2bfloat16(v.x); l0.x = __float2bfloat16(v.x - __bfloat162float(h0.x));
        h0.y = __float2bfloat16(v.y); l0.y = __float2bfloat16(v.y - __bfloat162float(h0.y));
        h1.x = __float2bfloat16(v.z); l1.x = __float2bfloat16(v.z - __bfloat162float(h1.x));
        h1.y = __float2bfloat16(v.w); l1.y = __float2bfloat16(v.w - __bfloat162float(h1.y));
        hi[2*i] = h0; hi[2*i+1] = h1;
        lo[2*i] = l0; lo[2*i+1] = l1;
    }
}

// ---------------------------------------------------------------------------
// Transpose + split: src[b][r][c] fp32 -> hi/lo[b][c][r] bf16.  64x64 tiles.
// Mask-bounded: tiles with r0 >= round32(lens[b]) produce s-positions the PV
// GEMM's K-clip never reads -> skip.
// ---------------------------------------------------------------------------
__global__ __launch_bounds__(256)
void transpose_split(const float* __restrict__ src, __nv_bfloat16* __restrict__ hi,
                     __nv_bfloat16* __restrict__ lo, int rows, int cols,
                     const int* __restrict__ lens)
{
    const int b = blockIdx.z;
    const int r0 = blockIdx.y * 64;
    if (lens) {
        const int L = lens[b];
        if (r0 >= ((L + 31) & ~31)) return;
    }
    __shared__ float t[64][65];
    const size_t off = (size_t)b * rows * cols;
    const int c0 = blockIdx.x * 64;
    const int tid = threadIdx.x;

#pragma unroll
    for (int i = 0; i < 4; i++) {
        int fi = tid + 256 * i;
        int lr = fi >> 4, lc4 = fi & 15;
        float4 v = *(const float4*)&src[off + (size_t)(r0 + lr) * cols + c0 + lc4 * 4];
        t[lr][lc4 * 4 + 0] = v.x;  t[lr][lc4 * 4 + 1] = v.y;
        t[lr][lc4 * 4 + 2] = v.z;  t[lr][lc4 * 4 + 3] = v.w;
    }
    __syncthreads();

#pragma unroll
    for (int i = 0; i < 8; i++) {
        int ci = tid + 256 * i;
        int oc = ci >> 5, rs = ci & 31;
        float v0 = t[rs * 2][oc], v1 = t[rs * 2 + 1][oc];
        __nv_bfloat162 h, l;
        h.x = __float2bfloat16(v0); l.x = __float2bfloat16(v0 - __bfloat162float(h.x));
        h.y = __float2bfloat16(v1); l.y = __float2bfloat16(v1 - __bfloat162float(h.y));
        size_t o = off + (size_t)(c0 + oc) * rows + r0 + rs * 2;
        *(__nv_bfloat162*)&hi[o] = h;
        *(__nv_bfloat162*)&lo[o] = l;
    }
}

// ---------------------------------------------------------------------------
// Masked softmax: fp32 scores -> split-bf16 P. Loads only s<L, stores s<round32(L).
// Warp-shuffle reductions (2 __syncthreads total).
// ---------------------------------------------------------------------------
__global__ __launch_bounds__(256)
void softmax_split(const float* __restrict__ S, __nv_bfloat16* __restrict__ Phi,
                   __nv_bfloat16* __restrict__ Plo, const int* __restrict__ lens)
{
    const int row = blockIdx.x;
    const int b   = row / LQ_;
    const int L   = lens[b];
    int Lr = (L + 31) & ~31;  Lr = Lr < LK_ ? Lr : LK_;
    const float* Sr = S + (size_t)row * LK_;
    __nv_bfloat16* Ph = Phi + (size_t)row * LK_;
    __nv_bfloat16* Pl = Plo + (size_t)row * LK_;

    const int tid = threadIdx.x, lane = tid & 31, wid = tid >> 5;
    __shared__ float red[8];

    float v[8];
    float m = -3.4e38f;
#pragma unroll
    for (int i = 0; i < 8; i++) {
        const int s = tid + i * 256;
        v[i] = (s < L) ? Sr[s] : 0.f;
        if (s < L) m = fmaxf(m, v[i]);
    }
#pragma unroll
    for (int o = 16; o > 0; o >>= 1)
        m = fmaxf(m, __shfl_xor_sync(0xFFFFFFFFu, m, o));
    if (lane == 0) red[wid] = m;
    __syncthreads();
    m = red[0];
#pragma unroll
    for (int w = 1; w < 8; w++) m = fmaxf(m, red[w]);
    __syncthreads();                      // protect red[] before reuse

    float sum = 0.f;
#pragma unroll
    for (int i = 0; i < 8; i++) {
        const int s = tid + i * 256;
        v[i] = (s < L) ? expf(v[i] - m) : 0.f;
        sum += v[i];
    }
#pragma unroll
    for (int o = 16; o > 0; o >>= 1)
        sum += __shfl_xor_sync(0xFFFFFFFFu, sum, o);
    if (lane == 0) red[wid] = sum;
    __syncthreads();
    float tot = red[0];
#pragma unroll
    for (int w = 1; w < 8; w++) tot += red[w];
    const float inv = 1.f / tot;

#pragma unroll
    for (int i = 0; i < 8; i++) {
        const int s = tid + i * 256;
        if (s < Lr) {
            float p = v[i] * inv;
            __nv_bfloat16 h = __float2bfloat16(p);
            Ph[s] = h;
            Pl[s] = __float2bfloat16(p - __bfloat162float(h));
        }
    }
}

// ---------------------------------------------------------------------------
// Launch:  Mt[b]=K[b]@W^T (skip masked rows) ; S=Q@Mt^T/32 (skip masked cols) ;
//          P=masked_softmax(S) ; out=P@V (K clipped at valid_len).  All bf16 3-pass.
// ---------------------------------------------------------------------------
extern "C" void kernel_launch(void* const* d_in, const int* in_sizes, int n_in,
                              void* d_out, int out_size)
{
    const float* queries = (const float*)d_in[0];
    const float* keys    = (const float*)d_in[1];
    const float* values  = (const float*)d_in[2];
    const int*   lens    = (const int*)  d_in[3];
    const float* Wq      = (const float*)d_in[4];
    float*       out     = (float*)d_out;

    void *pQhi, *pQlo, *pKhi, *pKlo, *pWhi, *pWlo, *pMthi, *pMtlo;
    void *pVthi, *pVtlo, *pS, *pPhi, *pPlo;
    cudaGetSymbolAddress(&pQhi,  g_Qhi);  cudaGetSymbolAddress(&pQlo,  g_Qlo);
    cudaGetSymbolAddress(&pKhi,  g_Khi);  cudaGetSymbolAddress(&pKlo,  g_Klo);
    cudaGetSymbolAddress(&pWhi,  g_Whi);  cudaGetSymbolAddress(&pWlo,  g_Wlo);
    cudaGetSymbolAddress(&pMthi, g_Mthi); cudaGetSymbolAddress(&pMtlo, g_Mtlo);
    cudaGetSymbolAddress(&pVthi, g_Vthi); cudaGetSymbolAddress(&pVtlo, g_Vtlo);
    cudaGetSymbolAddress(&pS,    g_S);
    cudaGetSymbolAddress(&pPhi,  g_Phi);  cudaGetSymbolAddress(&pPlo,  g_Plo);

    __nv_bfloat16 *Qhi = (__nv_bfloat16*)pQhi,  *Qlo = (__nv_bfloat16*)pQlo;
    __nv_bfloat16 *Khi = (__nv_bfloat16*)pKhi,  *Klo = (__nv_bfloat16*)pKlo;
    __nv_bfloat16 *Whi = (__nv_bfloat16*)pWhi,  *Wlo = (__nv_bfloat16*)pWlo;
    __nv_bfloat16 *Mthi = (__nv_bfloat16*)pMthi, *Mtlo = (__nv_bfloat16*)pMtlo;
    __nv_bfloat16 *Vthi = (__nv_bfloat16*)pVthi, *Vtlo = (__nv_bfloat16*)pVtlo;
    float *S = (float*)pS;
    __nv_bfloat16 *Phi = (__nv_bfloat16*)pPhi, *Plo = (__nv_bfloat16*)pPlo;

    cudaFuncSetAttribute(mma_gemm<true,  false, false, true >, cudaFuncAttributeMaxDynamicSharedMemorySize, GSMEM);
    cudaFuncSetAttribute(mma_gemm<false, true,  false, false>, cudaFuncAttributeMaxDynamicSharedMemorySize, GSMEM);
    cudaFuncSetAttribute(mma_gemm<false, false, true,  false>, cudaFuncAttributeMaxDynamicSharedMemorySize, GSMEM);

    // 0) prep: split Q, W (full); K rows bounded by mask; V transpose bounded
    split_kernel<<<2048, 256>>>((const float4*)queries, (__nv_bfloat162*)Qhi,
                                (__nv_bfloat162*)Qlo, NQ / 4);
    split_rows_kernel<<<dim3(LK_/4, B_), 256>>>((const float4*)keys,
                                (__nv_bfloat162*)Khi, (__nv_bfloat162*)Klo, lens);
    split_kernel<<<512, 256>>>((const float4*)Wq, (__nv_bfloat162*)Whi,
                               (__nv_bfloat162*)Wlo, NW / 4);
    transpose_split<<<dim3(DV_/64, LK_/64, B_), 256>>>(values, Vthi, Vtlo, LK_, DV_, lens);

    // 1) Mt[b] = K[b] @ W^T -> split bf16 [s][d]; skip M-tiles >= L
    mma_gemm<true, false, false, true><<<dim3(DK_/BN, LK_/BM, B_), 256, GSMEM>>>(
        Khi, Klo, Whi, Wlo, nullptr, Mthi, Mtlo,
        DK_, DK_,
        (long long)LK_ * DK_, 0LL, (long long)LK_ * DK_,
        1.0f, lens);

    // 2) S[b] = Q[b] @ Mt[b]^T / 32   (skip masked N-tiles)
    mma_gemm<false, true, false, false><<<dim3(LK_/BN, LQ_/BM, B_), 256, GSMEM>>>(
        Qhi, Qlo, Mthi, Mtlo, S, nullptr, nullptr,
        LK_, DQ_,
        (long long)LQ_ * DQ_, (long long)LK_ * DK_, (long long)LQ_ * LK_,
        0.03125f, lens);

    // 3) Masked softmax -> split bf16 P (bounded IO, shuffle reductions)
    softmax_split<<<B_ * LQ_, 256>>>(S, Phi, Plo, lens);

    // 4) out[b] = P[b] @ Vt[b]^T-form  (bf16 3-pass, K clipped at valid_len)
    mma_gemm<false, false, true, false><<<dim3(DV_/BN, LQ_/BM, B_), 256, GSMEM>>>(
        Phi, Plo, Vthi, Vtlo, out, nullptr, nullptr,
        DV_, LK_,
        (long long)LQ_ * LK_, (long long)DV_ * LK_, (long long)LQ_ * DV_,
        1.0f, lens);
}

// round 17
// speedup vs baseline: 1.0565x; 1.0069x over previous
#include <cuda_runtime.h>
#include <cuda_bf16.h>
#include <cstdint>

// ---------------------------------------------------------------------------
// Problem constants
// ---------------------------------------------------------------------------
#define B_   8
#define LQ_  2048
#define LK_  2048
#define DQ_  1024
#define DK_  1024
#define DV_  1024

constexpr size_t NQ  = (size_t)B_ * LQ_ * DQ_;
constexpr size_t NKV = (size_t)B_ * LK_ * DK_;
constexpr size_t NS  = (size_t)B_ * LQ_ * LK_;
constexpr size_t NW  = (size_t)DK_ * DQ_;
constexpr size_t NM  = (size_t)B_ * LK_ * DK_;   // Mt = K @ W^T : [b][s][d]

// Scratch (__device__ globals: allocation-free rule; zero-initialized)
__device__ __align__(256) __nv_bfloat16 g_Qhi[NQ],  g_Qlo[NQ];    // split queries
__device__ __align__(256) __nv_bfloat16 g_Khi[NKV], g_Klo[NKV];   // split keys
__device__ __align__(256) __nv_bfloat16 g_Whi[NW],  g_Wlo[NW];    // split Wq (native [d][k])
__device__ __align__(256) __nv_bfloat16 g_Mthi[NM], g_Mtlo[NM];   // split Mt [b][s][d]
__device__ __align__(256) __nv_bfloat16 g_Vthi[NKV], g_Vtlo[NKV]; // split values^T [b][v][s]
__device__ __align__(256) float         g_S[NS];                  // scores
__device__ __align__(256) __nv_bfloat16 g_Phi[NS], g_Plo[NS];     // split probs (bf16)

// ---------------------------------------------------------------------------
// Side stream + fork/join events.  Created ONCE at static-init time (before
// any capture).  No device memory involved; no per-call state -> kernel_launch
// stays deterministic and graph-capturable (multi-stream capture via the
// documented event fork/join pattern).
// ---------------------------------------------------------------------------
struct SideStream {
    cudaStream_t s;
    cudaEvent_t  e_fork, e_join;
    SideStream() {
        cudaStreamCreateWithFlags(&s, cudaStreamNonBlocking);
        cudaEventCreateWithFlags(&e_fork, cudaEventDisableTiming);
        cudaEventCreateWithFlags(&e_join, cudaEventDisableTiming);
    }
};
static SideStream g_side;

// ---------------------------------------------------------------------------
// Helpers
// ---------------------------------------------------------------------------
__device__ __forceinline__ unsigned smem_u32(const void* p) {
    unsigned r;
    asm("{.reg .u64 t; cvta.to.shared.u64 t, %1; cvt.u32.u64 %0, t;}" : "=r"(r) : "l"(p));
    return r;
}
#define SWZ(b) ((b) ^ (((b) >> 3) & 0x30))

#define CPA(dst, src) \
    asm volatile("cp.async.cg.shared.global [%0], [%1], 16;\n" :: "r"(dst), "l"(src))
#define LDSM4(r0, r1, r2, r3, addr) \
    asm volatile("ldmatrix.sync.aligned.m8n8.x4.shared.b16 {%0,%1,%2,%3}, [%4];\n" \
                 : "=r"(r0), "=r"(r1), "=r"(r2), "=r"(r3) : "r"(addr))
#define MMA(d, a, bb) \
    asm volatile("mma.sync.aligned.m16n8k16.row.col.f32.bf16.bf16.f32 " \
                 "{%0,%1,%2,%3},{%4,%5,%6,%7},{%8,%9},{%0,%1,%2,%3};\n" \
                 : "+f"((d)[0]), "+f"((d)[1]), "+f"((d)[2]), "+f"((d)[3]) \
                 : "r"((a)[0]), "r"((a)[1]), "r"((a)[2]), "r"((a)[3]), \
                   "r"((bb)[0]), "r"((bb)[1]))

// ---------------------------------------------------------------------------
// 3-pass split-bf16 GEMM:  C = alpha * (Ahi+Alo) @ (Bhi+Blo)^T  (A:[M,K], B:[N,K])
// BM=BN=128, BK=32, 256 threads, 8 warps (2x4), warp tile 64x32.
// cp.async 3-stage pipeline (32KB stages), SW64 swizzle, ldmatrix loads.
// __launch_bounds__(256, 2) pins the 2-CTA/SM regime.  ONE barrier per K-tile.
// Grid: x = N-tile, y = M-tile, z = batch.
// Passes: Ah*Bh + Al*Bh + Ah*Bl.
// SKIPM: skip M-tiles >= lens[b].  SKIPN: skip N-tiles >= lens[b].
// KBOUND: clip K loop to round32(lens[b]).  SPLITOUT: write hi/lo bf16 arrays.
// ---------------------------------------------------------------------------
constexpr int BM = 128, BN = 128;
constexpr int STAGE  = 32768;     // bytes per pipeline stage (4 x 8KB tiles)
constexpr int NSTG   = 3;
constexpr int OFF_AH = 0, OFF_AL = 8192, OFF_BH = 16384, OFF_BL = 24576;
constexpr int GSMEM  = NSTG * STAGE;   // 96 KB -> 2 CTAs/SM (192 <= 227 KB)

template<bool SKIPM, bool SKIPN, bool KBOUND, bool SPLITOUT>
__global__ __launch_bounds__(256, 2)
void mma_gemm(const __nv_bfloat16* __restrict__ Ahi, const __nv_bfloat16* __restrict__ Alo,
              const __nv_bfloat16* __restrict__ Bh,  const __nv_bfloat16* __restrict__ Bl,
              float* __restrict__ C,
              __nv_bfloat16* __restrict__ Chi, __nv_bfloat16* __restrict__ Clo,
              int N, int K,
              long long sA, long long sB, long long sC,
              float alpha, const int* __restrict__ lens)
{
    const int b = blockIdx.z;
    int L = 0;
    if (SKIPM || SKIPN || KBOUND) L = lens[b];
    if (SKIPM && (int)blockIdx.y * BM >= L) return;
    if (SKIPN && (int)blockIdx.x * BN >= L) return;
    int Keff = K;
    if (KBOUND) { int r = (L + 31) & ~31; Keff = r < K ? r : K; }
    const int ntiles = Keff >> 5;

    extern __shared__ char smem[];
    const unsigned sb = smem_u32(smem);

    const int tid = threadIdx.x, lane = tid & 31, wid = tid >> 5;
    const int wm = wid >> 2, wn = wid & 3;           // warp grid 2(m) x 4(n)
    const long long m0 = (long long)blockIdx.y * BM;
    const long long n0 = (long long)blockIdx.x * BN;

    Ahi += (long long)b * sA;  Alo += (long long)b * sA;
    Bh  += (long long)b * sB;  Bl  += (long long)b * sB;

    // ---- staging: thread owns 2 (row, 16B-chunk) slots per 128x32 tile ----
    const int srow = tid >> 2, sch = tid & 3;
    const unsigned d0 = SWZ((unsigned)(srow * 64 + sch * 16));
    const unsigned d1 = SWZ((unsigned)((srow + 64) * 64 + sch * 16));
    const __nv_bfloat16* pAh0 = Ahi + (m0 + srow)      * (long long)K + sch * 8;
    const __nv_bfloat16* pAh1 = Ahi + (m0 + srow + 64) * (long long)K + sch * 8;
    const __nv_bfloat16* pAl0 = Alo + (m0 + srow)      * (long long)K + sch * 8;
    const __nv_bfloat16* pAl1 = Alo + (m0 + srow + 64) * (long long)K + sch * 8;
    const __nv_bfloat16* pBh0 = Bh  + (n0 + srow)      * (long long)K + sch * 8;
    const __nv_bfloat16* pBh1 = Bh  + (n0 + srow + 64) * (long long)K + sch * 8;
    const __nv_bfloat16* pBl0 = Bl  + (n0 + srow)      * (long long)K + sch * 8;
    const __nv_bfloat16* pBl1 = Bl  + (n0 + srow + 64) * (long long)K + sch * 8;

#define ISSUE(stg, kt) do {                                                \
    unsigned s_ = sb + (unsigned)(stg) * STAGE; int ko_ = (kt) * 32;       \
    CPA(s_ + OFF_AH + d0, pAh0 + ko_); CPA(s_ + OFF_AH + d1, pAh1 + ko_); \
    CPA(s_ + OFF_AL + d0, pAl0 + ko_); CPA(s_ + OFF_AL + d1, pAl1 + ko_); \
    CPA(s_ + OFF_BH + d0, pBh0 + ko_); CPA(s_ + OFF_BH + d1, pBh1 + ko_); \
    CPA(s_ + OFF_BL + d0, pBl0 + ko_); CPA(s_ + OFF_BL + d1, pBl1 + ko_); \
    asm volatile("cp.async.commit_group;\n" ::); } while (0)

    float acc[4][4][4];
#pragma unroll
    for (int i = 0; i < 4; i++)
#pragma unroll
        for (int j = 0; j < 4; j++)
#pragma unroll
            for (int k = 0; k < 4; k++) acc[i][j][k] = 0.f;

    ISSUE(0, 0);
    if (ntiles > 1) ISSUE(1, 1);

    // fragment address components
    const int arow = lane & 15;
    const int ak2  = ((lane >> 4) & 1) * 16;
    const int g    = lane >> 3;
    const int brow = ((g >> 1) << 3) + (lane & 7);
    const int bk2  = (g & 1) * 16;

    for (int kt = 0; kt < ntiles; kt++) {
        if (kt + 1 < ntiles) asm volatile("cp.async.wait_group 1;\n" ::);
        else                 asm volatile("cp.async.wait_group 0;\n" ::);
        __syncthreads();
        if (kt + 2 < ntiles) ISSUE((kt + 2) % NSTG, kt + 2);
        const unsigned base = sb + (unsigned)(kt % NSTG) * STAGE;

#pragma unroll
        for (int ks = 0; ks < 2; ks++) {
            unsigned ah[4][4], al[4][4], bh[4][2], bl[4][2];
#pragma unroll
            for (int mi = 0; mi < 4; mi++) {
                int row = wm * 64 + mi * 16 + arow;
                unsigned sw = SWZ((unsigned)(row * 64 + ks * 32 + ak2));
                LDSM4(ah[mi][0], ah[mi][1], ah[mi][2], ah[mi][3], base + OFF_AH + sw);
                LDSM4(al[mi][0], al[mi][1], al[mi][2], al[mi][3], base + OFF_AL + sw);
            }
#pragma unroll
            for (int bi = 0; bi < 2; bi++) {
                int row = wn * 32 + bi * 16 + brow;
                unsigned sw = SWZ((unsigned)(row * 64 + ks * 32 + bk2));
                LDSM4(bh[2*bi][0], bh[2*bi][1], bh[2*bi+1][0], bh[2*bi+1][1], base + OFF_BH + sw);
                LDSM4(bl[2*bi][0], bl[2*bi][1], bl[2*bi+1][0], bl[2*bi+1][1], base + OFF_BL + sw);
            }
#pragma unroll
            for (int mi = 0; mi < 4; mi++)
#pragma unroll
                for (int ni = 0; ni < 4; ni++) MMA(acc[mi][ni], ah[mi], bh[ni]);
#pragma unroll
            for (int mi = 0; mi < 4; mi++)
#pragma unroll
                for (int ni = 0; ni < 4; ni++) MMA(acc[mi][ni], al[mi], bh[ni]);
#pragma unroll
            for (int mi = 0; mi < 4; mi++)
#pragma unroll
                for (int ni = 0; ni < 4; ni++) MMA(acc[mi][ni], ah[mi], bl[ni]);
        }
    }
#undef ISSUE

    // ---- epilogue ----
    const int erow = lane >> 2, ecol = (lane & 3) << 1;
#pragma unroll
    for (int mi = 0; mi < 4; mi++) {
        long long r0 = m0 + wm * 64 + mi * 16 + erow;
#pragma unroll
        for (int ni = 0; ni < 4; ni++) {
            long long c0 = n0 + wn * 32 + ni * 8 + ecol;
            float v0 = acc[mi][ni][0] * alpha, v1 = acc[mi][ni][1] * alpha;
            float v2 = acc[mi][ni][2] * alpha, v3 = acc[mi][ni][3] * alpha;
            size_t i0 = (size_t)((long long)b * sC + r0 * N + c0);
            size_t i1 = i0 + (size_t)8 * N;
            if (SPLITOUT) {
                __nv_bfloat162 h0, l0, h1, l1;
                h0.x = __float2bfloat16(v0); l0.x = __float2bfloat16(v0 - __bfloat162float(h0.x));
                h0.y = __float2bfloat16(v1); l0.y = __float2bfloat16(v1 - __bfloat162float(h0.y));
                h1.x = __float2bfloat16(v2); l1.x = __float2bfloat16(v2 - __bfloat162float(h1.x));
                h1.y = __float2bfloat16(v3); l1.y = __float2bfloat16(v3 - __bfloat162float(h1.y));
                *(__nv_bfloat162*)&Chi[i0] = h0;  *(__nv_bfloat162*)&Clo[i0] = l0;
                *(__nv_bfloat162*)&Chi[i1] = h1;  *(__nv_bfloat162*)&Clo[i1] = l1;
            } else {
                *(float2*)&C[i0] = make_float2(v0, v1);
                *(float2*)&C[i1] = make_float2(v2, v3);
            }
        }
    }
}

// ---------------------------------------------------------------------------
// Elementwise split: fp32 -> bf16 hi + bf16 lo (unbounded; Q and W)
// ---------------------------------------------------------------------------
__global__ __launch_bounds__(256)
void split_kernel(const float4* __restrict__ src, __nv_bfloat162* __restrict__ hi,
                  __nv_bfloat162* __restrict__ lo, size_t n4)
{
    size_t i = (size_t)blockIdx.x * blockDim.x + threadIdx.x;
    const size_t stride = (size_t)gridDim.x * blockDim.x;
    for (; i < n4; i += stride) {
        float4 v = src[i];
        __nv_bfloat162 h0, h1, l0, l1;
        h0.x = __float2bfloat16(v.x); l0.x = __float2bfloat16(v.x - __bfloat162float(h0.x));
        h0.y = __float2bfloat16(v.y); l0.y = __float2bfloat16(v.y - __bfloat162float(h0.y));
        h1.x = __float2bfloat16(v.z); l1.x = __float2bfloat16(v.z - __bfloat162float(h1.x));
        h1.y = __float2bfloat16(v.w); l1.y = __float2bfloat16(v.w - __bfloat162float(h1.y));
        hi[2*i] = h0; hi[2*i+1] = h1;
        lo[2*i] = l0; lo[2*i+1] = l1;
    }
}

// ---------------------------------------------------------------------------
// Mask-bounded row split for K [b][s][d]: rows s >= round128(lens[b]) are never
// read by the Mt GEMM (SKIPM) -> skip those blocks.  4 rows per block.
// ---------------------------------------------------------------------------
__global__ __launch_bounds__(256)
void split_rows_kernel(const float4* __restrict__ src, __nv_bfloat162* __restrict__ hi,
                       __nv_bfloat162* __restrict__ lo, const int* __restrict__ lens)
{
    const int b = blockIdx.y;
    const int row0 = blockIdx.x * 4;
    const int L = lens[b];
    if (row0 >= ((L + 127) & ~127)) return;

    constexpr int C4 = DK_ / 4;           // 256 float4 per row
    const size_t base = ((size_t)b * LK_ + row0) * C4;   // in float4 units
    const int tid = threadIdx.x;
#pragma unroll
    for (int j = 0; j < 4; j++) {
        size_t i = base + (size_t)j * 256 + tid;
        float4 v = src[i];
        __nv_bfloat162 h0, h1, l0, l1;
        h0.x = __float2bfloat16(v.x); l0.x = __float2bfloat16(v.x - __bfloat162float(h0.x));
        h0.y = __float2bfloat16(v.y); l0.y = __float2bfloat16(v.y - __bfloat162float(h0.y));
        h1.x = __float2bfloat16(v.z); l1.x = __float2bfloat16(v.z - __bfloat162float(h1.x));
        h1.y = __float2bfloat16(v.w); l1.y = __float2bfloat16(v.w - __bfloat162float(h1.y));
        hi[2*i] = h0; hi[2*i+1] = h1;
        lo[2*i] = l0; lo[2*i+1] = l1;
    }
}

// ---------------------------------------------------------------------------
// Transpose + split: src[b][r][c] fp32 -> hi/lo[b][c][r] bf16.  64x64 tiles.
// Mask-bounded: tiles with r0 >= round32(lens[b]) are never read by PV.
// ---------------------------------------------------------------------------
__global__ __launch_bounds__(256)
void transpose_split(const float* __restrict__ src, __nv_bfloat16* __restrict__ hi,
                     __nv_bfloat16* __restrict__ lo, int rows, int cols,
                     const int* __restrict__ lens)
{
    const int b = blockIdx.z;
    const int r0 = blockIdx.y * 64;
    if (lens) {
        const int L = lens[b];
        if (r0 >= ((L + 31) & ~31)) return;
    }
    __shared__ float t[64][65];
    const size_t off = (size_t)b * rows * cols;
    const int c0 = blockIdx.x * 64;
    const int tid = threadIdx.x;

#pragma unroll
    for (int i = 0; i < 4; i++) {
        int fi = tid + 256 * i;
        int lr = fi >> 4, lc4 = fi & 15;
        float4 v = *(const float4*)&src[off + (size_t)(r0 + lr) * cols + c0 + lc4 * 4];
        t[lr][lc4 * 4 + 0] = v.x;  t[lr][lc4 * 4 + 1] = v.y;
        t[lr][lc4 * 4 + 2] = v.z;  t[lr][lc4 * 4 + 3] = v.w;
    }
    __syncthreads();

#pragma unroll
    for (int i = 0; i < 8; i++) {
        int ci = tid + 256 * i;
        int oc = ci >> 5, rs = ci & 31;
        float v0 = t[rs * 2][oc], v1 = t[rs * 2 + 1][oc];
        __nv_bfloat162 h, l;
        h.x = __float2bfloat16(v0); l.x = __float2bfloat16(v0 - __bfloat162float(h.x));
        h.y = __float2bfloat16(v1); l.y = __float2bfloat16(v1 - __bfloat162float(h.y));
        size_t o = off + (size_t)(c0 + oc) * rows + r0 + rs * 2;
        *(__nv_bfloat162*)&hi[o] = h;
        *(__nv_bfloat162*)&lo[o] = l;
    }
}

// ---------------------------------------------------------------------------
// Masked softmax: fp32 scores -> split-bf16 P. Loads only s<L, stores s<round32(L).
// Warp-shuffle reductions (2 __syncthreads total).
// ---------------------------------------------------------------------------
__global__ __launch_bounds__(256)
void softmax_split(const float* __restrict__ S, __nv_bfloat16* __restrict__ Phi,
                   __nv_bfloat16* __restrict__ Plo, const int* __restrict__ lens)
{
    const int row = blockIdx.x;
    const int b   = row / LQ_;
    const int L   = lens[b];
    int Lr = (L + 31) & ~31;  Lr = Lr < LK_ ? Lr : LK_;
    const float* Sr = S + (size_t)row * LK_;
    __nv_bfloat16* Ph = Phi + (size_t)row * LK_;
    __nv_bfloat16* Pl = Plo + (size_t)row * LK_;

    const int tid = threadIdx.x, lane = tid & 31, wid = tid >> 5;
    __shared__ float red[8];

    float v[8];
    float m = -3.4e38f;
#pragma unroll
    for (int i = 0; i < 8; i++) {
        const int s = tid + i * 256;
        v[i] = (s < L) ? Sr[s] : 0.f;
        if (s < L) m = fmaxf(m, v[i]);
    }
#pragma unroll
    for (int o = 16; o > 0; o >>= 1)
        m = fmaxf(m, __shfl_xor_sync(0xFFFFFFFFu, m, o));
    if (lane == 0) red[wid] = m;
    __syncthreads();
    m = red[0];
#pragma unroll
    for (int w = 1; w < 8; w++) m = fmaxf(m, red[w]);
    __syncthreads();                      // protect red[] before reuse

    float sum = 0.f;
#pragma unroll
    for (int i = 0; i < 8; i++) {
        const int s = tid + i * 256;
        v[i] = (s < L) ? expf(v[i] - m) : 0.f;
        sum += v[i];
    }
#pragma unroll
    for (int o = 16; o > 0; o >>= 1)
        sum += __shfl_xor_sync(0xFFFFFFFFu, sum, o);
    if (lane == 0) red[wid] = sum;
    __syncthreads();
    float tot = red[0];
#pragma unroll
    for (int w = 1; w < 8; w++) tot += red[w];
    const float inv = 1.f / tot;

#pragma unroll
    for (int i = 0; i < 8; i++) {
        const int s = tid + i * 256;
        if (s < Lr) {
            float p = v[i] * inv;
            __nv_bfloat16 h = __float2bfloat16(p);
            Ph[s] = h;
            Pl[s] = __float2bfloat16(p - __bfloat162float(h));
        }
    }
}

// ---------------------------------------------------------------------------
// Launch.  Two capture-time branches:
//   main:  Ksplit -> Wsplit -> Mt GEMM ----\
//   side:  Qsplit -> Vtranspose ------------+--> scores -> softmax -> PV
// (Mt GEMM doesn't need Q or V; the side branch hides under it.)
// ---------------------------------------------------------------------------
extern "C" void kernel_launch(void* const* d_in, const int* in_sizes, int n_in,
                              void* d_out, int out_size)
{
    const float* queries = (const float*)d_in[0];
    const float* keys    = (const float*)d_in[1];
    const float* values  = (const float*)d_in[2];
    const int*   lens    = (const int*)  d_in[3];
    const float* Wq      = (const float*)d_in[4];
    float*       out     = (float*)d_out;

    void *pQhi, *pQlo, *pKhi, *pKlo, *pWhi, *pWlo, *pMthi, *pMtlo;
    void *pVthi, *pVtlo, *pS, *pPhi, *pPlo;
    cudaGetSymbolAddress(&pQhi,  g_Qhi);  cudaGetSymbolAddress(&pQlo,  g_Qlo);
    cudaGetSymbolAddress(&pKhi,  g_Khi);  cudaGetSymbolAddress(&pKlo,  g_Klo);
    cudaGetSymbolAddress(&pWhi,  g_Whi);  cudaGetSymbolAddress(&pWlo,  g_Wlo);
    cudaGetSymbolAddress(&pMthi, g_Mthi); cudaGetSymbolAddress(&pMtlo, g_Mtlo);
    cudaGetSymbolAddress(&pVthi, g_Vthi); cudaGetSymbolAddress(&pVtlo, g_Vtlo);
    cudaGetSymbolAddress(&pS,    g_S);
    cudaGetSymbolAddress(&pPhi,  g_Phi);  cudaGetSymbolAddress(&pPlo,  g_Plo);

    __nv_bfloat16 *Qhi = (__nv_bfloat16*)pQhi,  *Qlo = (__nv_bfloat16*)pQlo;
    __nv_bfloat16 *Khi = (__nv_bfloat16*)pKhi,  *Klo = (__nv_bfloat16*)pKlo;
    __nv_bfloat16 *Whi = (__nv_bfloat16*)pWhi,  *Wlo = (__nv_bfloat16*)pWlo;
    __nv_bfloat16 *Mthi = (__nv_bfloat16*)pMthi, *Mtlo = (__nv_bfloat16*)pMtlo;
    __nv_bfloat16 *Vthi = (__nv_bfloat16*)pVthi, *Vtlo = (__nv_bfloat16*)pVtlo;
    float *S = (float*)pS;
    __nv_bfloat16 *Phi = (__nv_bfloat16*)pPhi, *Plo = (__nv_bfloat16*)pPlo;

    cudaFuncSetAttribute(mma_gemm<true,  false, false, true >, cudaFuncAttributeMaxDynamicSharedMemorySize, GSMEM);
    cudaFuncSetAttribute(mma_gemm<false, true,  false, false>, cudaFuncAttributeMaxDynamicSharedMemorySize, GSMEM);
    cudaFuncSetAttribute(mma_gemm<false, false, true,  false>, cudaFuncAttributeMaxDynamicSharedMemorySize, GSMEM);

    // ---- fork side branch (Q split + V transpose; not needed until scores/PV)
    cudaEventRecord(g_side.e_fork, 0);
    cudaStreamWaitEvent(g_side.s, g_side.e_fork, 0);
    split_kernel<<<2048, 256, 0, g_side.s>>>((const float4*)queries,
                                (__nv_bfloat162*)Qhi, (__nv_bfloat162*)Qlo, NQ / 4);
    transpose_split<<<dim3(DV_/64, LK_/64, B_), 256, 0, g_side.s>>>(
                                values, Vthi, Vtlo, LK_, DV_, lens);
    cudaEventRecord(g_side.e_join, g_side.s);

    // ---- main branch: K split, W split, Mt GEMM
    split_rows_kernel<<<dim3(LK_/4, B_), 256>>>((const float4*)keys,
                                (__nv_bfloat162*)Khi, (__nv_bfloat162*)Klo, lens);
    split_kernel<<<512, 256>>>((const float4*)Wq, (__nv_bfloat162*)Whi,
                               (__nv_bfloat162*)Wlo, NW / 4);

    // 1) Mt[b] = K[b] @ W^T -> split bf16 [s][d]; skip M-tiles >= L
    mma_gemm<true, false, false, true><<<dim3(DK_/BN, LK_/BM, B_), 256, GSMEM>>>(
        Khi, Klo, Whi, Wlo, nullptr, Mthi, Mtlo,
        DK_, DK_,
        (long long)LK_ * DK_, 0LL, (long long)LK_ * DK_,
        1.0f, lens);

    // ---- join: scores needs Q (side); PV needs V (side)
    cudaStreamWaitEvent(0, g_side.e_join, 0);

    // 2) S[b] = Q[b] @ Mt[b]^T / 32   (skip masked N-tiles)
    mma_gemm<false, true, false, false><<<dim3(LK_/BN, LQ_/BM, B_), 256, GSMEM>>>(
        Qhi, Qlo, Mthi, Mtlo, S, nullptr, nullptr,
        LK_, DQ_,
        (long long)LQ_ * DQ_, (long long)LK_ * DK_, (long long)LQ_ * LK_,
        0.03125f, lens);

    // 3) Masked softmax -> split bf16 P (bounded IO, shuffle reductions)
    softmax_split<<<B_ * LQ_, 256>>>(S, Phi, Plo, lens);

    // 4) out[b] = P[b] @ Vt[b]^T-form  (bf16 3-pass, K clipped at valid_len)
    mma_gemm<false, false, true, false><<<dim3(DV_/BN, LQ_/BM, B_), 256, GSMEM>>>(
        Phi, Plo, Vthi, Vtlo, out, nullptr, nullptr,
        DV_, LK_,
        (long long)LQ_ * LK_, (long long)DV_ * LK_, (long long)LQ_ * DV_,
        1.0f, lens);
}